// round 11
// baseline (speedup 1.0000x reference)
#include <cuda_runtime.h>
#include <cuda_fp16.h>
#include <math.h>

// Problem dims (fixed by the reference)
#define BB   2
#define SEQ  2048
#define DIM  768
#define NH   12
#define DHD  64
#define FFD  3072
#define PDIM 64
#define PDPAD 128
#define NROW (BB*SEQ)      // 4096

#define STAGES 4
#define BKH    32                        // k-tile in halves
#define LDRH   40                        // padded row length in halves (80 B)
#define OPSTG  (128*LDRH*2)              // 10240 B per operand per stage
#define STAGE_BYTES (2*OPSTG)            // 20480
#define SMEM_DYN (STAGES*STAGE_BYTES)    // 81920

#define LOG2E 1.4426950408889634f

// ---------------- scratch (device globals; no cudaMalloc allowed) ----------
__device__ __align__(16) __half g_xn[NROW*DIM];
__device__ __align__(16) __half g_xnT[NROW*DIM];                  // [B][D][S]
__device__ __align__(16) __half g_qk[NROW*2*DIM];
__device__ __align__(16) __half g_phw[PDPAD*DIM];
__device__ __align__(16) __half g_phase[NROW*PDPAD];
__device__              float  g_ssum[BB*NH*SEQ];
__device__ __align__(16) __half g_blend[(size_t)BB*SEQ*SEQ];
__device__              float  g_rowsum[BB*SEQ];
__device__ __align__(16) float  g_xmid[NROW*DIM];                // residual: fp32
__device__ __align__(16) __half g_x2[NROW*DIM];
__device__ __align__(16) __half g_hbuf[NROW*FFD];
// fp16-rounded weight copies
__device__ __align__(16) __half g_inw[2*DIM*DIM];
__device__ __align__(16) __half g_w1[FFD*DIM];
__device__ __align__(16) __half g_w2[DIM*FFD];

// ---------------- helpers ----------------------------------------------------
__device__ __forceinline__ float warpReduceSum(float v) {
#pragma unroll
    for (int o = 16; o > 0; o >>= 1) v += __shfl_xor_sync(0xffffffffu, v, o);
    return v;
}
__device__ __forceinline__ float blockReduceSum256(float v, float* sm) {
    v = warpReduceSum(v);
    if ((threadIdx.x & 31) == 0) sm[threadIdx.x >> 5] = v;
    __syncthreads();
    if (threadIdx.x < 32) {
        float t = (threadIdx.x < 8) ? sm[threadIdx.x] : 0.0f;
        t = warpReduceSum(t);
        if (threadIdx.x == 0) sm[0] = t;
    }
    __syncthreads();
    float r = sm[0];
    __syncthreads();
    return r;
}

// exp via MUFU EX2: x assumed scaled by LOG2E already. rel err ~2.4e-7.
__device__ __forceinline__ float ex2f(float x) {
    float r;
    asm("ex2.approx.f32 %0, %1;" : "=f"(r) : "f"(x));
    return r;
}

__device__ __forceinline__ unsigned smem_u32(const void* p) {
    unsigned a;
    asm("{ .reg .u64 t; cvta.to.shared.u64 t, %1; cvt.u32.u64 %0, t; }"
        : "=r"(a) : "l"(p));
    return a;
}
__device__ __forceinline__ void cp_async16(unsigned dst, const void* src) {
    asm volatile("cp.async.cg.shared.global [%0], [%1], 16;" :: "r"(dst), "l"(src));
}
__device__ __forceinline__ void ldsm_x4(unsigned& r0, unsigned& r1,
                                        unsigned& r2, unsigned& r3, unsigned addr) {
    asm volatile("ldmatrix.sync.aligned.m8n8.x4.shared.b16 {%0,%1,%2,%3}, [%4];"
        : "=r"(r0), "=r"(r1), "=r"(r2), "=r"(r3) : "r"(addr));
}
__device__ __forceinline__ void mma_f16(float* c, const unsigned* a, const unsigned* b) {
    asm("mma.sync.aligned.m16n8k16.row.col.f32.f16.f16.f32 "
        "{%0,%1,%2,%3}, {%4,%5,%6,%7}, {%8,%9}, {%0,%1,%2,%3};"
        : "+f"(c[0]), "+f"(c[1]), "+f"(c[2]), "+f"(c[3])
        : "r"(a[0]), "r"(a[1]), "r"(a[2]), "r"(a[3]), "r"(b[0]), "r"(b[1]));
}

// ---------------- LayerNorm: fp32 in, fp16 out -------------------------------
__global__ void __launch_bounds__(256) ln_kernel(
    const float* __restrict__ x, const float* __restrict__ w,
    const float* __restrict__ b, __half* __restrict__ o)
{
    __shared__ float sm[8];
    const float* xr = x + (size_t)blockIdx.x * DIM;
    int t = threadIdx.x;
    float v0 = xr[t], v1 = xr[t + 256], v2 = xr[t + 512];
    float mean = blockReduceSum256(v0 + v1 + v2, sm) * (1.0f / DIM);
    float d0 = v0 - mean, d1 = v1 - mean, d2 = v2 - mean;
    float var = blockReduceSum256(d0*d0 + d1*d1 + d2*d2, sm) * (1.0f / DIM);
    float r = rsqrtf(var + 1e-5f);
    __half* orow = o + (size_t)blockIdx.x * DIM;
    orow[t      ] = __float2half_rn(d0 * r * w[t      ] + b[t      ]);
    orow[t + 256] = __float2half_rn(d1 * r * w[t + 256] + b[t + 256]);
    orow[t + 512] = __float2half_rn(d2 * r * w[t + 512] + b[t + 512]);
}

__global__ void __launch_bounds__(256) zero_kernel(float* __restrict__ p, int n) {
    int i = blockIdx.x * 256 + threadIdx.x;
    if (i < n) p[i] = 0.0f;
}

__global__ void __launch_bounds__(256) half_copy_kernel(
    const float* __restrict__ in, __half* __restrict__ o, int n)
{
    int i = blockIdx.x * 256 + threadIdx.x;
    if (i < n) o[i] = __float2half_rn(in[i]);
}

// pad phase_w [64,768] -> [128,768] with zeros, fp16
__global__ void __launch_bounds__(256) pad_phw_kernel(
    const float* __restrict__ w, __half* __restrict__ o)
{
    int i = blockIdx.x * 256 + threadIdx.x;
    if (i < PDPAD * DIM) o[i] = __float2half_rn((i < PDIM * DIM) ? w[i] : 0.0f);
}

// transpose per batch: in [SEQ][DIM] -> out [DIM][SEQ]  (fp16)
__global__ void __launch_bounds__(256) transpose_kernel(
    const __half* __restrict__ in, __half* __restrict__ out)
{
    __shared__ __half t[32][33];
    int b = blockIdx.z;
    const __half* ib = in + (size_t)b * SEQ * DIM;
    __half* ob = out + (size_t)b * SEQ * DIM;
    int tx = threadIdx.x & 31, ty = threadIdx.x >> 5;
    int sbase = blockIdx.x * 32;
    int dbase = blockIdx.y * 32;
#pragma unroll
    for (int i = 0; i < 32; i += 8)
        t[ty + i][tx] = ib[(size_t)(sbase + ty + i) * DIM + dbase + tx];
    __syncthreads();
#pragma unroll
    for (int i = 0; i < 32; i += 8)
        ob[(size_t)(dbase + ty + i) * SEQ + sbase + tx] = t[tx][ty + i];
}

// ============================================================================
// fp16 tensor-core GEMM: 128x128x32 CTA tile, 8 warps (2x4), warp 64x32,
// mma.sync m16n8k16 (f32 accum), 4-stage cp.async pipeline, ldmatrix.x4.
// A [M,K] half row-major, B [N,K] half row-major: C = A @ B^T.
// EPI: 1=+bias->h, 2=tanh->h, 3=bias+GELU->h, 4=bias+residual->f,
//      5=row-divide(rowsum)+residual->f,
//      8=ex2(scale*v) + atomic rowsum, NO C store (stats-only pass)
// ============================================================================
template<int EPI> struct OutT { using T = __half; };
template<> struct OutT<4> { using T = float; };
template<> struct OutT<5> { using T = float; };

template<int EPI>
__global__ void __launch_bounds__(256, 2) tgemm(
    const __half* __restrict__ A, const __half* __restrict__ Bm,
    typename OutT<EPI>::T* __restrict__ C,
    int M, int N, int K, int lda, int ldb, int ldc,
    int zdiv,
    long as1, long as2, long bs1, long bs2, long cs1, long cs2,
    float scale,
    const float* __restrict__ bias,
    const float* __restrict__ res, long ress1,
    const float* __restrict__ rsum, long rsums1,
    float* __restrict__ ssum)
{
    constexpr bool OUTH = (EPI != 4 && EPI != 5);
    extern __shared__ char sh[];

    int z = blockIdx.z;
    int z1 = z / zdiv, z2 = z - z1 * zdiv;
    A  += z1 * as1 + z2 * as2;
    Bm += z1 * bs1 + z2 * bs2;
    if (EPI != 8) C += z1 * cs1 + z2 * cs2;
    if (EPI == 4 || EPI == 5) res  += z1 * ress1;
    if (EPI == 5)             rsum += z1 * rsums1;
    if (EPI == 8)             ssum += (size_t)z * M;

    int tid  = threadIdx.x;
    int lane = tid & 31;
    int wid  = tid >> 5;
    int wm   = (wid & 1) * 64;
    int wn   = (wid >> 1) * 32;
    int g    = lane >> 2;
    int tg   = lane & 3;
    int bm = blockIdx.x * 128, bn = blockIdx.y * 128;

    float acc[4][4][4];
#pragma unroll
    for (int i = 0; i < 4; i++)
#pragma unroll
        for (int j = 0; j < 4; j++)
#pragma unroll
            for (int r = 0; r < 4; r++) acc[i][j][r] = 0.0f;

    // cp.async staging: thread -> row tid/2, 2x16B at half-col (tid&1)*16
    int r0 = tid >> 1;
    int hc = (tid & 1) << 4;                 // 0 or 16 halves
    unsigned base = smem_u32(sh);
    unsigned aDst = base + (unsigned)r0 * (LDRH * 2) + hc * 2;
    unsigned bDst = aDst + OPSTG;
    const __half* aSrc = A + (size_t)(bm + r0) * lda + hc;
    const __half* bSrc = Bm + (size_t)(bn + r0) * ldb + hc;

    // ldmatrix per-lane addresses (stage 0, ks 0); b16 8x8 rows = 16B
    int mi = lane >> 3, lr = lane & 7;
    unsigned aAddr[4], bAddr[2];
#pragma unroll
    for (int mt = 0; mt < 4; mt++)
        aAddr[mt] = base + (unsigned)(wm + mt * 16 + (mi & 1) * 8 + lr) * (LDRH * 2)
                  + (mi >> 1) * 16;
#pragma unroll
    for (int p = 0; p < 2; p++)
        bAddr[p] = base + OPSTG
                 + (unsigned)(wn + (p * 2 + (mi >> 1)) * 8 + lr) * (LDRH * 2)
                 + (mi & 1) * 16;

    auto stage_load = [&](int t, int T) {
        if (t < T) {
            unsigned so = (unsigned)(t % STAGES) * STAGE_BYTES;
            int k0 = t * BKH;
            cp_async16(aDst + so,      aSrc + k0);
            cp_async16(aDst + so + 16, aSrc + k0 + 8);
            cp_async16(bDst + so,      bSrc + k0);
            cp_async16(bDst + so + 16, bSrc + k0 + 8);
        }
        asm volatile("cp.async.commit_group;");
    };

    int T = K / BKH;
    stage_load(0, T);
    stage_load(1, T);
    stage_load(2, T);

    int s = 0;
    for (int t = 0; t < T; t++) {
        asm volatile("cp.async.wait_group 2;");
        __syncthreads();
        stage_load(t + 3, T);

        unsigned so = (unsigned)s * STAGE_BYTES;
#pragma unroll
        for (int ks = 0; ks < 2; ks++) {
            unsigned kofs = so + ks * 32;    // 16 halves per k16 step
            unsigned afr[4][4], bfr[4][2];
#pragma unroll
            for (int mt = 0; mt < 4; mt++)
                ldsm_x4(afr[mt][0], afr[mt][1], afr[mt][2], afr[mt][3],
                        aAddr[mt] + kofs);
            ldsm_x4(bfr[0][0], bfr[0][1], bfr[1][0], bfr[1][1], bAddr[0] + kofs);
            ldsm_x4(bfr[2][0], bfr[2][1], bfr[3][0], bfr[3][1], bAddr[1] + kofs);
#pragma unroll
            for (int mt = 0; mt < 4; mt++)
#pragma unroll
                for (int nt = 0; nt < 4; nt++)
                    mma_f16(acc[mt][nt], afr[mt], bfr[nt]);
        }
        if (++s >= STAGES) s = 0;
    }

    // ---------------- epilogue ----------------
#pragma unroll
    for (int mt = 0; mt < 4; mt++) {
#pragma unroll
        for (int half = 0; half < 2; half++) {
            int m = bm + wm + mt * 16 + g + half * 8;
            float rinv = 0.0f;
            if (EPI == 5) rinv = 1.0f / rsum[m];
            float rs = 0.0f;
#pragma unroll
            for (int nt = 0; nt < 4; nt++) {
                int c = bn + wn + nt * 8 + tg * 2;
                float v0 = acc[mt][nt][half * 2];
                float v1 = acc[mt][nt][half * 2 + 1];
                if (EPI == 1) { v0 += bias[c]; v1 += bias[c + 1]; }
                if (EPI == 2) { v0 = tanhf(v0); v1 = tanhf(v1); }
                if (EPI == 3) {
                    v0 += bias[c]; v1 += bias[c + 1];
                    v0 = 0.5f * v0 * (1.0f + erff(v0 * 0.70710678118654752f));
                    v1 = 0.5f * v1 * (1.0f + erff(v1 * 0.70710678118654752f));
                }
                if (EPI == 4) {
                    const float2 rr = *(const float2*)(res + (size_t)m * ldc + c);
                    v0 += bias[c] + rr.x; v1 += bias[c + 1] + rr.y;
                }
                if (EPI == 5) {
                    const float2 rr = *(const float2*)(res + (size_t)m * ldc + c);
                    v0 = v0 * rinv + rr.x; v1 = v1 * rinv + rr.y;
                }
                if (EPI == 8) { v0 = ex2f(v0 * scale); v1 = ex2f(v1 * scale); rs += v0 + v1; }
                if (EPI != 8) {
                    if constexpr (OUTH) {
                        *(__half2*)(C + (size_t)m * ldc + c) = __floats2half2_rn(v0, v1);
                    } else {
                        float2 o; o.x = v0; o.y = v1;
                        *(float2*)(C + (size_t)m * ldc + c) = o;
                    }
                }
            }
            if (EPI == 8) {
                rs += __shfl_xor_sync(0xffffffffu, rs, 1);
                rs += __shfl_xor_sync(0xffffffffu, rs, 2);
                if (tg == 0) atomicAdd(&ssum[m], rs);
            }
        }
    }
}

// ============================================================================
// fused_blend: for tile (b, i, j), recompute 12 head-score GEMMs + the
// phase-coherence GEMM (all K=64) through one 26-k-tile cp.async pipeline.
// w = 1e-6 + sum_h ex2(scaleq*s_h) * sinvl[h][row];  u = w * ex2(a2l*(pc+1))
// Stores u (fp16) and atomically accumulates row sums.
// ============================================================================
__global__ void __launch_bounds__(256) fused_blend(
    const __half* __restrict__ qk, const __half* __restrict__ phase,
    const float* __restrict__ ssum, const float* __restrict__ alphap,
    __half* __restrict__ blend, float* __restrict__ rowsum)
{
    extern __shared__ char sh[];
    __shared__ float sinvl[NH][128];

    int b  = blockIdx.z;
    int bm = blockIdx.x * 128;     // i tile (rows)
    int bn = blockIdx.y * 128;     // j tile (cols)

    int tid  = threadIdx.x;
    int lane = tid & 31;
    int wid  = tid >> 5;
    int wm   = (wid & 1) * 64;
    int wn   = (wid >> 1) * 32;
    int g    = lane >> 2;
    int tg   = lane & 3;

    // per-row, per-head 1/(12*ssum)
    for (int i = tid; i < NH * 128; i += 256) {
        int h = i >> 7, r = i & 127;
        sinvl[h][r] = 1.0f / (ssum[(size_t)(b * NH + h) * SEQ + bm + r] * (float)NH);
    }

    const float scaleq = 0.125f * LOG2E;
    const float a2l    = 0.5f * (*alphap) * LOG2E;

    float acc[4][4][4];
    float w[4][4][4];
#pragma unroll
    for (int i = 0; i < 4; i++)
#pragma unroll
        for (int j = 0; j < 4; j++)
#pragma unroll
            for (int r = 0; r < 4; r++) { acc[i][j][r] = 0.0f; w[i][j][r] = 1e-6f; }

    // staging
    int r0 = tid >> 1;
    int hc = (tid & 1) << 4;
    unsigned base = smem_u32(sh);
    unsigned aDst = base + (unsigned)r0 * (LDRH * 2) + hc * 2;
    unsigned bDst = aDst + OPSTG;
    const __half* aQ = qk + (size_t)(b * SEQ + bm + r0) * (2 * DIM) + hc;          // q part
    const __half* bK = qk + (size_t)(b * SEQ + bn + r0) * (2 * DIM) + DIM + hc;    // k part
    const __half* aP = phase + (size_t)(b * SEQ + bm + r0) * PDPAD + hc;
    const __half* bP = phase + (size_t)(b * SEQ + bn + r0) * PDPAD + hc;

    int mi = lane >> 3, lr = lane & 7;
    unsigned aAddr[4], bAddr[2];
#pragma unroll
    for (int mt = 0; mt < 4; mt++)
        aAddr[mt] = base + (unsigned)(wm + mt * 16 + (mi & 1) * 8 + lr) * (LDRH * 2)
                  + (mi >> 1) * 16;
#pragma unroll
    for (int p = 0; p < 2; p++)
        bAddr[p] = base + OPSTG
                 + (unsigned)(wn + (p * 2 + (mi >> 1)) * 8 + lr) * (LDRH * 2)
                 + (mi & 1) * 16;

    // 26 k-tiles: t<24 -> head seg=t/2 (q/k cols 32t); t in {24,25} -> phase
    auto stage_load = [&](int t) {
        if (t < 26) {
            unsigned so = (unsigned)(t & 3) * STAGE_BYTES;
            const __half *as, *bs;
            if (t < 24) { as = aQ + t * 32;        bs = bK + t * 32; }
            else        { as = aP + (t - 24) * 32; bs = bP + (t - 24) * 32; }
            cp_async16(aDst + so,      as);
            cp_async16(aDst + so + 16, as + 8);
            cp_async16(bDst + so,      bs);
            cp_async16(bDst + so + 16, bs + 8);
        }
        asm volatile("cp.async.commit_group;");
    };

    stage_load(0); stage_load(1); stage_load(2);

    for (int t = 0; t < 26; t++) {
        asm volatile("cp.async.wait_group 2;");
        __syncthreads();
        stage_load(t + 3);

        unsigned so = (unsigned)(t & 3) * STAGE_BYTES;
#pragma unroll
        for (int ks = 0; ks < 2; ks++) {
            unsigned kofs = so + ks * 32;
            unsigned afr[4][4], bfr[4][2];
#pragma unroll
            for (int mt = 0; mt < 4; mt++)
                ldsm_x4(afr[mt][0], afr[mt][1], afr[mt][2], afr[mt][3],
                        aAddr[mt] + kofs);
            ldsm_x4(bfr[0][0], bfr[0][1], bfr[1][0], bfr[1][1], bAddr[0] + kofs);
            ldsm_x4(bfr[2][0], bfr[2][1], bfr[3][0], bfr[3][1], bAddr[1] + kofs);
#pragma unroll
            for (int mt = 0; mt < 4; mt++)
#pragma unroll
                for (int nt = 0; nt < 4; nt++)
                    mma_f16(acc[mt][nt], afr[mt], bfr[nt]);
        }

        if ((t & 1) && t < 24) {
            int seg = t >> 1;      // head index
#pragma unroll
            for (int mt = 0; mt < 4; mt++)
#pragma unroll
                for (int half = 0; half < 2; half++) {
                    float sl = sinvl[seg][wm + mt * 16 + g + half * 8];
#pragma unroll
                    for (int nt = 0; nt < 4; nt++)
#pragma unroll
                        for (int j2 = 0; j2 < 2; j2++) {
                            int r = half * 2 + j2;
                            w[mt][nt][r] = fmaf(ex2f(acc[mt][nt][r] * scaleq), sl,
                                                w[mt][nt][r]);
                            acc[mt][nt][r] = 0.0f;
                        }
                }
        }
    }

    // acc now holds phase@phase^T tile; finish u and store
#pragma unroll
    for (int mt = 0; mt < 4; mt++) {
#pragma unroll
        for (int half = 0; half < 2; half++) {
            int m = bm + wm + mt * 16 + g + half * 8;
            float rs = 0.0f;
#pragma unroll
            for (int nt = 0; nt < 4; nt++) {
                int c = bn + wn + nt * 8 + tg * 2;
                float p0 = ex2f(fmaf(acc[mt][nt][half * 2],     a2l, a2l));
                float p1 = ex2f(fmaf(acc[mt][nt][half * 2 + 1], a2l, a2l));
                float u0 = w[mt][nt][half * 2]     * p0;
                float u1 = w[mt][nt][half * 2 + 1] * p1;
                rs += u0 + u1;
                *(__half2*)(blend + (size_t)(b * SEQ + m) * SEQ + c) =
                    __floats2half2_rn(u0, u1);
            }
            rs += __shfl_xor_sync(0xffffffffu, rs, 1);
            rs += __shfl_xor_sync(0xffffffffu, rs, 2);
            if (tg == 0) atomicAdd(&rowsum[b * SEQ + m], rs);
        }
    }
}

// ---------------------------------------------------------------------------
extern "C" void kernel_launch(void* const* d_in, const int* in_sizes, int n_in,
                              void* d_out, int out_size)
{
    const float* x        = (const float*)d_in[0];
    const float* ln1_w    = (const float*)d_in[1];
    const float* ln1_b    = (const float*)d_in[2];
    const float* in_w     = (const float*)d_in[3];
    const float* in_b     = (const float*)d_in[4];
    const float* phase_w  = (const float*)d_in[5];
    const float* alpha    = (const float*)d_in[6];
    const float* ff_w1    = (const float*)d_in[7];
    const float* ff_b1    = (const float*)d_in[8];
    const float* ff_w2    = (const float*)d_in[9];
    const float* ff_b2    = (const float*)d_in[10];
    const float* ln2_w    = (const float*)d_in[11];
    const float* ln2_b    = (const float*)d_in[12];
    float* out            = (float*)d_out;

    __half *xn, *xnT, *qk, *phw, *phase, *blend, *x2, *hbuf, *inw, *w1, *w2;
    float *ssum, *rowsum, *xmid;
    cudaGetSymbolAddress((void**)&xn,     g_xn);
    cudaGetSymbolAddress((void**)&xnT,    g_xnT);
    cudaGetSymbolAddress((void**)&qk,     g_qk);
    cudaGetSymbolAddress((void**)&phw,    g_phw);
    cudaGetSymbolAddress((void**)&phase,  g_phase);
    cudaGetSymbolAddress((void**)&ssum,   g_ssum);
    cudaGetSymbolAddress((void**)&blend,  g_blend);
    cudaGetSymbolAddress((void**)&rowsum, g_rowsum);
    cudaGetSymbolAddress((void**)&xmid,   g_xmid);
    cudaGetSymbolAddress((void**)&x2,     g_x2);
    cudaGetSymbolAddress((void**)&hbuf,   g_hbuf);
    cudaGetSymbolAddress((void**)&inw,    g_inw);
    cudaGetSymbolAddress((void**)&w1,     g_w1);
    cudaGetSymbolAddress((void**)&w2,     g_w2);

    cudaFuncSetAttribute(tgemm<1>, cudaFuncAttributeMaxDynamicSharedMemorySize, SMEM_DYN);
    cudaFuncSetAttribute(tgemm<2>, cudaFuncAttributeMaxDynamicSharedMemorySize, SMEM_DYN);
    cudaFuncSetAttribute(tgemm<3>, cudaFuncAttributeMaxDynamicSharedMemorySize, SMEM_DYN);
    cudaFuncSetAttribute(tgemm<4>, cudaFuncAttributeMaxDynamicSharedMemorySize, SMEM_DYN);
    cudaFuncSetAttribute(tgemm<5>, cudaFuncAttributeMaxDynamicSharedMemorySize, SMEM_DYN);
    cudaFuncSetAttribute(tgemm<8>, cudaFuncAttributeMaxDynamicSharedMemorySize, SMEM_DYN);
    cudaFuncSetAttribute(fused_blend, cudaFuncAttributeMaxDynamicSharedMemorySize, SMEM_DYN);

    // 0) fp16 round-to-nearest weight copies
    half_copy_kernel<<<(2*DIM*DIM + 255)/256, 256>>>(in_w, inw, 2*DIM*DIM);
    half_copy_kernel<<<(FFD*DIM + 255)/256, 256>>>(ff_w1, w1, FFD*DIM);
    half_copy_kernel<<<(DIM*FFD + 255)/256, 256>>>(ff_w2, w2, DIM*FFD);

    // 1) xn = LN1(x) -> fp16; xnT; zero sums; pad+round phase_w
    ln_kernel<<<NROW, 256>>>(x, ln1_w, ln1_b, xn);
    zero_kernel<<<(BB*NH*SEQ + 255)/256, 256>>>(ssum, BB*NH*SEQ);
    zero_kernel<<<(BB*SEQ + 255)/256, 256>>>(rowsum, BB*SEQ);
    pad_phw_kernel<<<(PDPAD*DIM + 255)/256, 256>>>(phase_w, phw);
    transpose_kernel<<<dim3(SEQ/32, DIM/32, BB), 256>>>(xn, xnT);

    // 2) qk = xn @ W[0:1536]^T + b -> fp16   [4096, 1536]
    tgemm<1><<<dim3(NROW/128, 1536/128, 1), 256, SMEM_DYN>>>(
        xn, inw, qk, NROW, 2*DIM, DIM, DIM, DIM, 2*DIM,
        1, 0,0, 0,0, 0,0, 1.0f, in_b, nullptr, 0, nullptr, 0, nullptr);

    // 3) phase = tanh(xn @ phw^T) -> fp16    [4096, 128] (cols 64..127 = 0)
    tgemm<2><<<dim3(NROW/128, 1, 1), 256, SMEM_DYN>>>(
        xn, phw, phase, NROW, PDPAD, DIM, DIM, DIM, PDPAD,
        1, 0,0, 0,0, 0,0, 1.0f, nullptr, nullptr, 0, nullptr, 0, nullptr);

    // 4) pass 1: per-head exp-score row sums (no score store)  24x[2048,2048]
    tgemm<8><<<dim3(SEQ/128, SEQ/128, BB*NH), 256, SMEM_DYN>>>(
        qk, qk + DIM, (__half*)nullptr, SEQ, SEQ, DHD, 2*DIM, 2*DIM, SEQ,
        NH, (long)SEQ*2*DIM, (long)DHD, (long)SEQ*2*DIM, (long)DHD,
            (long)NH*SEQ*SEQ, (long)SEQ*SEQ,
        0.125f * LOG2E, nullptr, nullptr, 0, nullptr, 0, ssum);

    // 5) pass 2: fused blend (recompute scores + pc, store u + rowsums)
    fused_blend<<<dim3(SEQ/128, SEQ/128, BB), 256, SMEM_DYN>>>(
        qk, phase, ssum, alpha, blend, rowsum);

    // 6) xmid = x + (blend/rowsum) @ xnT^T -> fp32   2x[2048, 768], K=2048
    tgemm<5><<<dim3(SEQ/128, DIM/128, BB), 256, SMEM_DYN>>>(
        blend, xnT, xmid, SEQ, DIM, SEQ, SEQ, SEQ, DIM,
        1, (long)SEQ*SEQ, 0, (long)DIM*SEQ, 0, (long)SEQ*DIM, 0,
        1.0f, nullptr, x, (long)SEQ*DIM, rowsum, (long)SEQ, nullptr);

    // 7) x2 = LN2(xmid) -> fp16
    ln_kernel<<<NROW, 256>>>(xmid, ln2_w, ln2_b, x2);

    // 8) h = gelu(x2 @ ff_w1^T + b1) -> fp16  [4096, 3072]
    tgemm<3><<<dim3(NROW/128, FFD/128, 1), 256, SMEM_DYN>>>(
        x2, w1, hbuf, NROW, FFD, DIM, DIM, DIM, FFD,
        1, 0,0, 0,0, 0,0, 1.0f, ff_b1, nullptr, 0, nullptr, 0, nullptr);

    // 9) out = xmid + h @ ff_w2^T + b2 -> fp32  [4096, 768], K=3072
    tgemm<4><<<dim3(NROW/128, DIM/128, 1), 256, SMEM_DYN>>>(
        hbuf, w2, out, NROW, DIM, FFD, FFD, FFD, DIM,
        1, 0,0, 0,0, 0,0, 1.0f, ff_b2, xmid, 0, nullptr, 0, nullptr);

    (void)in_sizes; (void)n_in; (void)out_size;
}

// round 13
// speedup vs baseline: 1.0254x; 1.0254x over previous
#include <cuda_runtime.h>
#include <cuda_fp16.h>
#include <math.h>

// Problem dims (fixed by the reference)
#define BB   2
#define SEQ  2048
#define DIM  768
#define NH   12
#define DHD  64
#define FFD  3072
#define PDIM 64
#define PDPAD 128
#define NROW (BB*SEQ)      // 4096

#define STAGES 4
#define BKH    32                        // k-tile in halves
#define LDRH   40                        // padded row length in halves (80 B)
#define OPSTG  (128*LDRH*2)              // 10240 B per operand per stage
#define STAGE_BYTES (2*OPSTG)            // 20480
#define SMEM_DYN (STAGES*STAGE_BYTES)    // 81920

// fused_blend (128x64 tile) smem layout
#define FB_BSTG  (64*LDRH*2)             // 5120
#define FB_STAGE (OPSTG + FB_BSTG)       // 15360
#define FB_SMEM  (4*FB_STAGE)            // 61440

#define LOG2E 1.4426950408889634f

// ---------------- scratch (device globals; no cudaMalloc allowed) ----------
__device__ __align__(16) __half g_xn[NROW*DIM];
__device__ __align__(16) __half g_xnT[NROW*DIM];                  // [B][D][S]
__device__ __align__(16) __half g_qk[NROW*2*DIM];
__device__ __align__(16) __half g_phw[PDPAD*DIM];
__device__ __align__(16) __half g_phase[NROW*PDPAD];
__device__              float  g_ssum[BB*NH*SEQ];
__device__ __align__(16) __half g_blend[(size_t)BB*SEQ*SEQ];
__device__              float  g_rowsum[BB*SEQ];
__device__ __align__(16) float  g_xmid[NROW*DIM];                // residual: fp32
__device__ __align__(16) __half g_x2[NROW*DIM];
__device__ __align__(16) __half g_hbuf[NROW*FFD];
// fp16-rounded weight copies
__device__ __align__(16) __half g_inw[2*DIM*DIM];
__device__ __align__(16) __half g_w1[FFD*DIM];
__device__ __align__(16) __half g_w2[DIM*FFD];

// ---------------- helpers ----------------------------------------------------
__device__ __forceinline__ float warpReduceSum(float v) {
#pragma unroll
    for (int o = 16; o > 0; o >>= 1) v += __shfl_xor_sync(0xffffffffu, v, o);
    return v;
}
__device__ __forceinline__ float blockReduceSum256(float v, float* sm) {
    v = warpReduceSum(v);
    if ((threadIdx.x & 31) == 0) sm[threadIdx.x >> 5] = v;
    __syncthreads();
    if (threadIdx.x < 32) {
        float t = (threadIdx.x < 8) ? sm[threadIdx.x] : 0.0f;
        t = warpReduceSum(t);
        if (threadIdx.x == 0) sm[0] = t;
    }
    __syncthreads();
    float r = sm[0];
    __syncthreads();
    return r;
}

// exp via MUFU EX2: x assumed scaled by LOG2E already. rel err ~2.4e-7.
__device__ __forceinline__ float ex2f(float x) {
    float r;
    asm("ex2.approx.f32 %0, %1;" : "=f"(r) : "f"(x));
    return r;
}

__device__ __forceinline__ unsigned smem_u32(const void* p) {
    unsigned a;
    asm("{ .reg .u64 t; cvta.to.shared.u64 t, %1; cvt.u32.u64 %0, t; }"
        : "=r"(a) : "l"(p));
    return a;
}
__device__ __forceinline__ void cp_async16(unsigned dst, const void* src) {
    asm volatile("cp.async.cg.shared.global [%0], [%1], 16;" :: "r"(dst), "l"(src));
}
__device__ __forceinline__ void ldsm_x4(unsigned& r0, unsigned& r1,
                                        unsigned& r2, unsigned& r3, unsigned addr) {
    asm volatile("ldmatrix.sync.aligned.m8n8.x4.shared.b16 {%0,%1,%2,%3}, [%4];"
        : "=r"(r0), "=r"(r1), "=r"(r2), "=r"(r3) : "r"(addr));
}
__device__ __forceinline__ void mma_f16(float* c, const unsigned* a, const unsigned* b) {
    asm("mma.sync.aligned.m16n8k16.row.col.f32.f16.f16.f32 "
        "{%0,%1,%2,%3}, {%4,%5,%6,%7}, {%8,%9}, {%0,%1,%2,%3};"
        : "+f"(c[0]), "+f"(c[1]), "+f"(c[2]), "+f"(c[3])
        : "r"(a[0]), "r"(a[1]), "r"(a[2]), "r"(a[3]), "r"(b[0]), "r"(b[1]));
}

// ---------------- LayerNorm: fp32 in, fp16 out -------------------------------
__global__ void __launch_bounds__(256) ln_kernel(
    const float* __restrict__ x, const float* __restrict__ w,
    const float* __restrict__ b, __half* __restrict__ o)
{
    __shared__ float sm[8];
    const float* xr = x + (size_t)blockIdx.x * DIM;
    int t = threadIdx.x;
    float v0 = xr[t], v1 = xr[t + 256], v2 = xr[t + 512];
    float mean = blockReduceSum256(v0 + v1 + v2, sm) * (1.0f / DIM);
    float d0 = v0 - mean, d1 = v1 - mean, d2 = v2 - mean;
    float var = blockReduceSum256(d0*d0 + d1*d1 + d2*d2, sm) * (1.0f / DIM);
    float r = rsqrtf(var + 1e-5f);
    __half* orow = o + (size_t)blockIdx.x * DIM;
    orow[t      ] = __float2half_rn(d0 * r * w[t      ] + b[t      ]);
    orow[t + 256] = __float2half_rn(d1 * r * w[t + 256] + b[t + 256]);
    orow[t + 512] = __float2half_rn(d2 * r * w[t + 512] + b[t + 512]);
}

__global__ void __launch_bounds__(256) zero_kernel(float* __restrict__ p, int n) {
    int i = blockIdx.x * 256 + threadIdx.x;
    if (i < n) p[i] = 0.0f;
}

__global__ void __launch_bounds__(256) half_copy_kernel(
    const float* __restrict__ in, __half* __restrict__ o, int n)
{
    int i = blockIdx.x * 256 + threadIdx.x;
    if (i < n) o[i] = __float2half_rn(in[i]);
}

// pad phase_w [64,768] -> [128,768] with zeros, fp16
__global__ void __launch_bounds__(256) pad_phw_kernel(
    const float* __restrict__ w, __half* __restrict__ o)
{
    int i = blockIdx.x * 256 + threadIdx.x;
    if (i < PDPAD * DIM) o[i] = __float2half_rn((i < PDIM * DIM) ? w[i] : 0.0f);
}

// transpose per batch: in [SEQ][DIM] -> out [DIM][SEQ]  (fp16)
__global__ void __launch_bounds__(256) transpose_kernel(
    const __half* __restrict__ in, __half* __restrict__ out)
{
    __shared__ __half t[32][33];
    int b = blockIdx.z;
    const __half* ib = in + (size_t)b * SEQ * DIM;
    __half* ob = out + (size_t)b * SEQ * DIM;
    int tx = threadIdx.x & 31, ty = threadIdx.x >> 5;
    int sbase = blockIdx.x * 32;
    int dbase = blockIdx.y * 32;
#pragma unroll
    for (int i = 0; i < 32; i += 8)
        t[ty + i][tx] = ib[(size_t)(sbase + ty + i) * DIM + dbase + tx];
    __syncthreads();
#pragma unroll
    for (int i = 0; i < 32; i += 8)
        ob[(size_t)(dbase + ty + i) * SEQ + sbase + tx] = t[tx][ty + i];
}

// ============================================================================
// fp16 tensor-core GEMM: 128x128x32 CTA tile, 8 warps (2x4), warp 64x32,
// mma.sync m16n8k16 (f32 accum), 4-stage cp.async pipeline, ldmatrix.x4.
// A [M,K] half row-major, B [N,K] half row-major: C = A @ B^T.
// EPI: 1=+bias->h, 2=tanh->h, 3=bias+GELU->h, 4=bias+residual->f,
//      5=row-divide(rowsum)+residual->f,
//      8=ex2(scale*v) + atomic rowsum, NO C store (stats-only pass)
// ============================================================================
template<int EPI> struct OutT { using T = __half; };
template<> struct OutT<4> { using T = float; };
template<> struct OutT<5> { using T = float; };

template<int EPI>
__global__ void __launch_bounds__(256, 2) tgemm(
    const __half* __restrict__ A, const __half* __restrict__ Bm,
    typename OutT<EPI>::T* __restrict__ C,
    int M, int N, int K, int lda, int ldb, int ldc,
    int zdiv,
    long as1, long as2, long bs1, long bs2, long cs1, long cs2,
    float scale,
    const float* __restrict__ bias,
    const float* __restrict__ res, long ress1,
    const float* __restrict__ rsum, long rsums1,
    float* __restrict__ ssum)
{
    constexpr bool OUTH = (EPI != 4 && EPI != 5);
    extern __shared__ char sh[];

    int z = blockIdx.z;
    int z1 = z / zdiv, z2 = z - z1 * zdiv;
    A  += z1 * as1 + z2 * as2;
    Bm += z1 * bs1 + z2 * bs2;
    if (EPI != 8) C += z1 * cs1 + z2 * cs2;
    if (EPI == 4 || EPI == 5) res  += z1 * ress1;
    if (EPI == 5)             rsum += z1 * rsums1;
    if (EPI == 8)             ssum += (size_t)z * M;

    int tid  = threadIdx.x;
    int lane = tid & 31;
    int wid  = tid >> 5;
    int wm   = (wid & 1) * 64;
    int wn   = (wid >> 1) * 32;
    int g    = lane >> 2;
    int tg   = lane & 3;
    int bm = blockIdx.x * 128, bn = blockIdx.y * 128;

    float acc[4][4][4];
#pragma unroll
    for (int i = 0; i < 4; i++)
#pragma unroll
        for (int j = 0; j < 4; j++)
#pragma unroll
            for (int r = 0; r < 4; r++) acc[i][j][r] = 0.0f;

    // cp.async staging: thread -> row tid/2, 2x16B at half-col (tid&1)*16
    int r0 = tid >> 1;
    int hc = (tid & 1) << 4;                 // 0 or 16 halves
    unsigned base = smem_u32(sh);
    unsigned aDst = base + (unsigned)r0 * (LDRH * 2) + hc * 2;
    unsigned bDst = aDst + OPSTG;
    const __half* aSrc = A + (size_t)(bm + r0) * lda + hc;
    const __half* bSrc = Bm + (size_t)(bn + r0) * ldb + hc;

    // ldmatrix per-lane addresses (stage 0, ks 0); b16 8x8 rows = 16B
    int mi = lane >> 3, lr = lane & 7;
    unsigned aAddr[4], bAddr[2];
#pragma unroll
    for (int mt = 0; mt < 4; mt++)
        aAddr[mt] = base + (unsigned)(wm + mt * 16 + (mi & 1) * 8 + lr) * (LDRH * 2)
                  + (mi >> 1) * 16;
#pragma unroll
    for (int p = 0; p < 2; p++)
        bAddr[p] = base + OPSTG
                 + (unsigned)(wn + (p * 2 + (mi >> 1)) * 8 + lr) * (LDRH * 2)
                 + (mi & 1) * 16;

    auto stage_load = [&](int t, int T) {
        if (t < T) {
            unsigned so = (unsigned)(t % STAGES) * STAGE_BYTES;
            int k0 = t * BKH;
            cp_async16(aDst + so,      aSrc + k0);
            cp_async16(aDst + so + 16, aSrc + k0 + 8);
            cp_async16(bDst + so,      bSrc + k0);
            cp_async16(bDst + so + 16, bSrc + k0 + 8);
        }
        asm volatile("cp.async.commit_group;");
    };

    int T = K / BKH;
    stage_load(0, T);
    stage_load(1, T);
    stage_load(2, T);

    int s = 0;
    for (int t = 0; t < T; t++) {
        asm volatile("cp.async.wait_group 2;");
        __syncthreads();
        stage_load(t + 3, T);

        unsigned so = (unsigned)s * STAGE_BYTES;
#pragma unroll
        for (int ks = 0; ks < 2; ks++) {
            unsigned kofs = so + ks * 32;    // 16 halves per k16 step
            unsigned afr[4][4], bfr[4][2];
#pragma unroll
            for (int mt = 0; mt < 4; mt++)
                ldsm_x4(afr[mt][0], afr[mt][1], afr[mt][2], afr[mt][3],
                        aAddr[mt] + kofs);
            ldsm_x4(bfr[0][0], bfr[0][1], bfr[1][0], bfr[1][1], bAddr[0] + kofs);
            ldsm_x4(bfr[2][0], bfr[2][1], bfr[3][0], bfr[3][1], bAddr[1] + kofs);
#pragma unroll
            for (int mt = 0; mt < 4; mt++)
#pragma unroll
                for (int nt = 0; nt < 4; nt++)
                    mma_f16(acc[mt][nt], afr[mt], bfr[nt]);
        }
        if (++s >= STAGES) s = 0;
    }

    // ---------------- epilogue ----------------
#pragma unroll
    for (int mt = 0; mt < 4; mt++) {
#pragma unroll
        for (int half = 0; half < 2; half++) {
            int m = bm + wm + mt * 16 + g + half * 8;
            float rinv = 0.0f;
            if (EPI == 5) rinv = 1.0f / rsum[m];
            float rs = 0.0f;
#pragma unroll
            for (int nt = 0; nt < 4; nt++) {
                int c = bn + wn + nt * 8 + tg * 2;
                float v0 = acc[mt][nt][half * 2];
                float v1 = acc[mt][nt][half * 2 + 1];
                if (EPI == 1) { v0 += bias[c]; v1 += bias[c + 1]; }
                if (EPI == 2) { v0 = tanhf(v0); v1 = tanhf(v1); }
                if (EPI == 3) {
                    v0 += bias[c]; v1 += bias[c + 1];
                    v0 = 0.5f * v0 * (1.0f + erff(v0 * 0.70710678118654752f));
                    v1 = 0.5f * v1 * (1.0f + erff(v1 * 0.70710678118654752f));
                }
                if (EPI == 4) {
                    const float2 rr = *(const float2*)(res + (size_t)m * ldc + c);
                    v0 += bias[c] + rr.x; v1 += bias[c + 1] + rr.y;
                }
                if (EPI == 5) {
                    const float2 rr = *(const float2*)(res + (size_t)m * ldc + c);
                    v0 = v0 * rinv + rr.x; v1 = v1 * rinv + rr.y;
                }
                if (EPI == 8) { v0 = ex2f(v0 * scale); v1 = ex2f(v1 * scale); rs += v0 + v1; }
                if (EPI != 8) {
                    if constexpr (OUTH) {
                        *(__half2*)(C + (size_t)m * ldc + c) = __floats2half2_rn(v0, v1);
                    } else {
                        float2 o; o.x = v0; o.y = v1;
                        *(float2*)(C + (size_t)m * ldc + c) = o;
                    }
                }
            }
            if (EPI == 8) {
                rs += __shfl_xor_sync(0xffffffffu, rs, 1);
                rs += __shfl_xor_sync(0xffffffffu, rs, 2);
                if (tg == 0) atomicAdd(&ssum[m], rs);
            }
        }
    }
}

// ============================================================================
// fused_blend (128x64 tile): recompute 12 head-score GEMMs + phase-coherence
// GEMM (all K=64) through one 26-k-tile cp.async pipeline; warp tile 64x16.
// w = 1e-6 + sum_h ex2(scaleq*s_h) * sinvl[h][row];  u = w * ex2(a2l*(pc+1))
// Stores u (fp16) and atomically accumulates row sums.
// ============================================================================
__global__ void __launch_bounds__(256, 2) fused_blend(
    const __half* __restrict__ qk, const __half* __restrict__ phase,
    const float* __restrict__ ssum, const float* __restrict__ alphap,
    __half* __restrict__ blend, float* __restrict__ rowsum)
{
    extern __shared__ char sh[];
    __shared__ float sinvl[NH][128];

    int b  = blockIdx.z;
    int bm = blockIdx.x * 128;     // i tile (rows)
    int bn = blockIdx.y * 64;      // j tile (cols)

    int tid  = threadIdx.x;
    int lane = tid & 31;
    int wid  = tid >> 5;
    int wm   = (wid & 1) * 64;
    int wn   = (wid >> 1) * 16;
    int g    = lane >> 2;
    int tg   = lane & 3;

    // per-row, per-head 1/(12*ssum)
    for (int i = tid; i < NH * 128; i += 256) {
        int h = i >> 7, r = i & 127;
        sinvl[h][r] = 1.0f / (ssum[(size_t)(b * NH + h) * SEQ + bm + r] * (float)NH);
    }

    const float scaleq = 0.125f * LOG2E;
    const float a2l    = 0.5f * (*alphap) * LOG2E;

    float acc[4][2][4];
    float w[4][2][4];
#pragma unroll
    for (int i = 0; i < 4; i++)
#pragma unroll
        for (int j = 0; j < 2; j++)
#pragma unroll
            for (int r = 0; r < 4; r++) { acc[i][j][r] = 0.0f; w[i][j][r] = 1e-6f; }

    // staging: A 128 rows (2 thr/row, 2x16B), B 64 rows (4 thr/row, 1x16B)
    int r0 = tid >> 1;
    int hc = (tid & 1) << 4;
    int rb  = tid >> 2;
    int cbh = (tid & 3) * 8;
    unsigned base = smem_u32(sh);
    unsigned aDst = base + (unsigned)r0 * (LDRH * 2) + hc * 2;
    unsigned bDst = base + OPSTG + (unsigned)rb * (LDRH * 2) + cbh * 2;
    const __half* aQ = qk + (size_t)(b * SEQ + bm + r0) * (2 * DIM) + hc;          // q
    const __half* aP = phase + (size_t)(b * SEQ + bm + r0) * PDPAD + hc;
    const __half* bK = qk + (size_t)(b * SEQ + bn + rb) * (2 * DIM) + DIM + cbh;   // k
    const __half* bP = phase + (size_t)(b * SEQ + bn + rb) * PDPAD + cbh;

    int mi = lane >> 3, lr = lane & 7;
    unsigned aAddr[4], bAddr;
#pragma unroll
    for (int mt = 0; mt < 4; mt++)
        aAddr[mt] = base + (unsigned)(wm + mt * 16 + (mi & 1) * 8 + lr) * (LDRH * 2)
                  + (mi >> 1) * 16;
    bAddr = base + OPSTG
          + (unsigned)(wn + (mi >> 1) * 8 + lr) * (LDRH * 2) + (mi & 1) * 16;

    // 26 k-tiles: t<24 -> head seg=t/2 (q/k cols 32t); t in {24,25} -> phase
    auto stage_load = [&](int t) {
        if (t < 26) {
            unsigned so = (unsigned)(t & 3) * FB_STAGE;
            const __half *as, *bs;
            if (t < 24) { as = aQ + t * 32;        bs = bK + t * 32; }
            else        { as = aP + (t - 24) * 32; bs = bP + (t - 24) * 32; }
            cp_async16(aDst + so,      as);
            cp_async16(aDst + so + 16, as + 8);
            cp_async16(bDst + so,      bs);
        }
        asm volatile("cp.async.commit_group;");
    };

    stage_load(0); stage_load(1); stage_load(2);

    for (int t = 0; t < 26; t++) {
        asm volatile("cp.async.wait_group 2;");
        __syncthreads();
        stage_load(t + 3);

        unsigned so = (unsigned)(t & 3) * FB_STAGE;
#pragma unroll
        for (int ks = 0; ks < 2; ks++) {
            unsigned kofs = so + ks * 32;
            unsigned afr[4][4], bfr[2][2];
#pragma unroll
            for (int mt = 0; mt < 4; mt++)
                ldsm_x4(afr[mt][0], afr[mt][1], afr[mt][2], afr[mt][3],
                        aAddr[mt] + kofs);
            ldsm_x4(bfr[0][0], bfr[0][1], bfr[1][0], bfr[1][1], bAddr + kofs);
#pragma unroll
            for (int mt = 0; mt < 4; mt++)
#pragma unroll
                for (int nt = 0; nt < 2; nt++)
                    mma_f16(acc[mt][nt], afr[mt], bfr[nt]);
        }

        if ((t & 1) && t < 24) {
            int seg = t >> 1;      // head index
#pragma unroll
            for (int mt = 0; mt < 4; mt++)
#pragma unroll
                for (int half = 0; half < 2; half++) {
                    float sl = sinvl[seg][wm + mt * 16 + g + half * 8];
#pragma unroll
                    for (int nt = 0; nt < 2; nt++)
#pragma unroll
                        for (int j2 = 0; j2 < 2; j2++) {
                            int r = half * 2 + j2;
                            w[mt][nt][r] = fmaf(ex2f(acc[mt][nt][r] * scaleq), sl,
                                                w[mt][nt][r]);
                            acc[mt][nt][r] = 0.0f;
                        }
                }
        }
    }

    // acc now holds phase@phase^T tile; finish u and store
#pragma unroll
    for (int mt = 0; mt < 4; mt++) {
#pragma unroll
        for (int half = 0; half < 2; half++) {
            int m = bm + wm + mt * 16 + g + half * 8;
            float rs = 0.0f;
#pragma unroll
            for (int nt = 0; nt < 2; nt++) {
                int c = bn + wn + nt * 8 + tg * 2;
                float p0 = ex2f(fmaf(acc[mt][nt][half * 2],     a2l, a2l));
                float p1 = ex2f(fmaf(acc[mt][nt][half * 2 + 1], a2l, a2l));
                float u0 = w[mt][nt][half * 2]     * p0;
                float u1 = w[mt][nt][half * 2 + 1] * p1;
                rs += u0 + u1;
                *(__half2*)(blend + (size_t)(b * SEQ + m) * SEQ + c) =
                    __floats2half2_rn(u0, u1);
            }
            rs += __shfl_xor_sync(0xffffffffu, rs, 1);
            rs += __shfl_xor_sync(0xffffffffu, rs, 2);
            if (tg == 0) atomicAdd(&rowsum[b * SEQ + m], rs);
        }
    }
}

// ---------------------------------------------------------------------------
extern "C" void kernel_launch(void* const* d_in, const int* in_sizes, int n_in,
                              void* d_out, int out_size)
{
    const float* x        = (const float*)d_in[0];
    const float* ln1_w    = (const float*)d_in[1];
    const float* ln1_b    = (const float*)d_in[2];
    const float* in_w     = (const float*)d_in[3];
    const float* in_b     = (const float*)d_in[4];
    const float* phase_w  = (const float*)d_in[5];
    const float* alpha    = (const float*)d_in[6];
    const float* ff_w1    = (const float*)d_in[7];
    const float* ff_b1    = (const float*)d_in[8];
    const float* ff_w2    = (const float*)d_in[9];
    const float* ff_b2    = (const float*)d_in[10];
    const float* ln2_w    = (const float*)d_in[11];
    const float* ln2_b    = (const float*)d_in[12];
    float* out            = (float*)d_out;

    __half *xn, *xnT, *qk, *phw, *phase, *blend, *x2, *hbuf, *inw, *w1, *w2;
    float *ssum, *rowsum, *xmid;
    cudaGetSymbolAddress((void**)&xn,     g_xn);
    cudaGetSymbolAddress((void**)&xnT,    g_xnT);
    cudaGetSymbolAddress((void**)&qk,     g_qk);
    cudaGetSymbolAddress((void**)&phw,    g_phw);
    cudaGetSymbolAddress((void**)&phase,  g_phase);
    cudaGetSymbolAddress((void**)&ssum,   g_ssum);
    cudaGetSymbolAddress((void**)&blend,  g_blend);
    cudaGetSymbolAddress((void**)&rowsum, g_rowsum);
    cudaGetSymbolAddress((void**)&xmid,   g_xmid);
    cudaGetSymbolAddress((void**)&x2,     g_x2);
    cudaGetSymbolAddress((void**)&hbuf,   g_hbuf);
    cudaGetSymbolAddress((void**)&inw,    g_inw);
    cudaGetSymbolAddress((void**)&w1,     g_w1);
    cudaGetSymbolAddress((void**)&w2,     g_w2);

    cudaFuncSetAttribute(tgemm<1>, cudaFuncAttributeMaxDynamicSharedMemorySize, SMEM_DYN);
    cudaFuncSetAttribute(tgemm<2>, cudaFuncAttributeMaxDynamicSharedMemorySize, SMEM_DYN);
    cudaFuncSetAttribute(tgemm<3>, cudaFuncAttributeMaxDynamicSharedMemorySize, SMEM_DYN);
    cudaFuncSetAttribute(tgemm<4>, cudaFuncAttributeMaxDynamicSharedMemorySize, SMEM_DYN);
    cudaFuncSetAttribute(tgemm<5>, cudaFuncAttributeMaxDynamicSharedMemorySize, SMEM_DYN);
    cudaFuncSetAttribute(tgemm<8>, cudaFuncAttributeMaxDynamicSharedMemorySize, SMEM_DYN);
    cudaFuncSetAttribute(fused_blend, cudaFuncAttributeMaxDynamicSharedMemorySize, FB_SMEM);

    // 0) fp16 round-to-nearest weight copies
    half_copy_kernel<<<(2*DIM*DIM + 255)/256, 256>>>(in_w, inw, 2*DIM*DIM);
    half_copy_kernel<<<(FFD*DIM + 255)/256, 256>>>(ff_w1, w1, FFD*DIM);
    half_copy_kernel<<<(DIM*FFD + 255)/256, 256>>>(ff_w2, w2, DIM*FFD);

    // 1) xn = LN1(x) -> fp16; xnT; zero sums; pad+round phase_w
    ln_kernel<<<NROW, 256>>>(x, ln1_w, ln1_b, xn);
    zero_kernel<<<(BB*NH*SEQ + 255)/256, 256>>>(ssum, BB*NH*SEQ);
    zero_kernel<<<(BB*SEQ + 255)/256, 256>>>(rowsum, BB*SEQ);
    pad_phw_kernel<<<(PDPAD*DIM + 255)/256, 256>>>(phase_w, phw);
    transpose_kernel<<<dim3(SEQ/32, DIM/32, BB), 256>>>(xn, xnT);

    // 2) qk = xn @ W[0:1536]^T + b -> fp16   [4096, 1536]
    tgemm<1><<<dim3(NROW/128, 1536/128, 1), 256, SMEM_DYN>>>(
        xn, inw, qk, NROW, 2*DIM, DIM, DIM, DIM, 2*DIM,
        1, 0,0, 0,0, 0,0, 1.0f, in_b, nullptr, 0, nullptr, 0, nullptr);

    // 3) phase = tanh(xn @ phw^T) -> fp16    [4096, 128] (cols 64..127 = 0)
    tgemm<2><<<dim3(NROW/128, 1, 1), 256, SMEM_DYN>>>(
        xn, phw, phase, NROW, PDPAD, DIM, DIM, DIM, PDPAD,
        1, 0,0, 0,0, 0,0, 1.0f, nullptr, nullptr, 0, nullptr, 0, nullptr);

    // 4) pass 1: per-head exp-score row sums (no score store)  24x[2048,2048]
    tgemm<8><<<dim3(SEQ/128, SEQ/128, BB*NH), 256, SMEM_DYN>>>(
        qk, qk + DIM, (__half*)nullptr, SEQ, SEQ, DHD, 2*DIM, 2*DIM, SEQ,
        NH, (long)SEQ*2*DIM, (long)DHD, (long)SEQ*2*DIM, (long)DHD,
            (long)NH*SEQ*SEQ, (long)SEQ*SEQ,
        0.125f * LOG2E, nullptr, nullptr, 0, nullptr, 0, ssum);

    // 5) pass 2: fused blend (recompute scores + pc, store u + rowsums)
    fused_blend<<<dim3(SEQ/128, SEQ/64, BB), 256, FB_SMEM>>>(
        qk, phase, ssum, alpha, blend, rowsum);

    // 6) xmid = x + (blend/rowsum) @ xnT^T -> fp32   2x[2048, 768], K=2048
    tgemm<5><<<dim3(SEQ/128, DIM/128, BB), 256, SMEM_DYN>>>(
        blend, xnT, xmid, SEQ, DIM, SEQ, SEQ, SEQ, DIM,
        1, (long)SEQ*SEQ, 0, (long)DIM*SEQ, 0, (long)SEQ*DIM, 0,
        1.0f, nullptr, x, (long)SEQ*DIM, rowsum, (long)SEQ, nullptr);

    // 7) x2 = LN2(xmid) -> fp16
    ln_kernel<<<NROW, 256>>>(xmid, ln2_w, ln2_b, x2);

    // 8) h = gelu(x2 @ ff_w1^T + b1) -> fp16  [4096, 3072]
    tgemm<3><<<dim3(NROW/128, FFD/128, 1), 256, SMEM_DYN>>>(
        x2, w1, hbuf, NROW, FFD, DIM, DIM, DIM, FFD,
        1, 0,0, 0,0, 0,0, 1.0f, ff_b1, nullptr, 0, nullptr, 0, nullptr);

    // 9) out = xmid + h @ ff_w2^T + b2 -> fp32  [4096, 768], K=3072
    tgemm<4><<<dim3(NROW/128, DIM/128, 1), 256, SMEM_DYN>>>(
        hbuf, w2, out, NROW, DIM, FFD, FFD, FFD, DIM,
        1, 0,0, 0,0, 0,0, 1.0f, ff_b2, xmid, 0, nullptr, 0, nullptr);

    (void)in_sizes; (void)n_in; (void)out_size;
}

// round 14
// speedup vs baseline: 1.0582x; 1.0320x over previous
#include <cuda_runtime.h>
#include <cuda_fp16.h>
#include <math.h>

// Problem dims (fixed by the reference)
#define BB   2
#define SEQ  2048
#define DIM  768
#define NH   12
#define DHD  64
#define FFD  3072
#define PDIM 64
#define PDPAD 128
#define NROW (BB*SEQ)      // 4096

#define STAGES 4
#define BKH    32                        // k-tile in halves
#define LDRH   40                        // padded row length in halves (80 B)
#define OPSTG  (128*LDRH*2)              // 10240 B per operand per stage
#define STAGE_BYTES (2*OPSTG)            // 20480
#define SMEM_DYN (STAGES*STAGE_BYTES)    // 81920

#define LOG2E 1.4426950408889634f

// ---------------- scratch (device globals; no cudaMalloc allowed) ----------
__device__ __align__(16) __half g_xn[NROW*DIM];
__device__ __align__(16) __half g_xnT[NROW*DIM];                  // [B][D][S]
__device__ __align__(16) __half g_qk[NROW*2*DIM];
__device__ __align__(16) __half g_phw[PDPAD*DIM];
__device__ __align__(16) __half g_phase[NROW*PDPAD];
__device__ __align__(16) __half g_scores[(size_t)BB*NH*SEQ*SEQ]; // exp(s/8) fp16
__device__              float  g_ssum[BB*NH*SEQ];
__device__ __align__(16) __half g_pc[(size_t)BB*SEQ*SEQ];        // exp(a*(pc+1)/2)
__device__ __align__(16) __half g_blend[(size_t)BB*SEQ*SEQ];
__device__              float  g_rowsum[BB*SEQ];
__device__ __align__(16) float  g_xmid[NROW*DIM];                // residual: fp32
__device__ __align__(16) __half g_x2[NROW*DIM];
__device__ __align__(16) __half g_hbuf[NROW*FFD];
// fp16-rounded weight copies
__device__ __align__(16) __half g_inw[2*DIM*DIM];
__device__ __align__(16) __half g_w1[FFD*DIM];
__device__ __align__(16) __half g_w2[DIM*FFD];

// ---------------- helpers ----------------------------------------------------
__device__ __forceinline__ float warpReduceSum(float v) {
#pragma unroll
    for (int o = 16; o > 0; o >>= 1) v += __shfl_xor_sync(0xffffffffu, v, o);
    return v;
}
__device__ __forceinline__ float blockReduceSum256(float v, float* sm) {
    v = warpReduceSum(v);
    if ((threadIdx.x & 31) == 0) sm[threadIdx.x >> 5] = v;
    __syncthreads();
    if (threadIdx.x < 32) {
        float t = (threadIdx.x < 8) ? sm[threadIdx.x] : 0.0f;
        t = warpReduceSum(t);
        if (threadIdx.x == 0) sm[0] = t;
    }
    __syncthreads();
    float r = sm[0];
    __syncthreads();
    return r;
}

// exp via MUFU EX2: x assumed scaled by LOG2E already. rel err ~2.4e-7.
__device__ __forceinline__ float ex2f(float x) {
    float r;
    asm("ex2.approx.f32 %0, %1;" : "=f"(r) : "f"(x));
    return r;
}

__device__ __forceinline__ unsigned smem_u32(const void* p) {
    unsigned a;
    asm("{ .reg .u64 t; cvta.to.shared.u64 t, %1; cvt.u32.u64 %0, t; }"
        : "=r"(a) : "l"(p));
    return a;
}
__device__ __forceinline__ void cp_async16(unsigned dst, const void* src) {
    asm volatile("cp.async.cg.shared.global [%0], [%1], 16;" :: "r"(dst), "l"(src));
}
__device__ __forceinline__ void ldsm_x4(unsigned& r0, unsigned& r1,
                                        unsigned& r2, unsigned& r3, unsigned addr) {
    asm volatile("ldmatrix.sync.aligned.m8n8.x4.shared.b16 {%0,%1,%2,%3}, [%4];"
        : "=r"(r0), "=r"(r1), "=r"(r2), "=r"(r3) : "r"(addr));
}
__device__ __forceinline__ void mma_f16(float* c, const unsigned* a, const unsigned* b) {
    asm("mma.sync.aligned.m16n8k16.row.col.f32.f16.f16.f32 "
        "{%0,%1,%2,%3}, {%4,%5,%6,%7}, {%8,%9}, {%0,%1,%2,%3};"
        : "+f"(c[0]), "+f"(c[1]), "+f"(c[2]), "+f"(c[3])
        : "r"(a[0]), "r"(a[1]), "r"(a[2]), "r"(a[3]), "r"(b[0]), "r"(b[1]));
}

// ---------------- LayerNorm: fp32 in, fp16 out (float4 vectorized) ----------
__global__ void __launch_bounds__(256) ln_kernel(
    const float* __restrict__ x, const float* __restrict__ w,
    const float* __restrict__ b, __half* __restrict__ o)
{
    __shared__ float sm[8];
    const float* xr = x + (size_t)blockIdx.x * DIM;
    int t = threadIdx.x;
    float4 v = {0.0f, 0.0f, 0.0f, 0.0f};
    if (t < 192) v = *(const float4*)(xr + t * 4);
    float mean = blockReduceSum256(v.x + v.y + v.z + v.w, sm) * (1.0f / DIM);
    float d0 = v.x - mean, d1 = v.y - mean, d2 = v.z - mean, d3 = v.w - mean;
    float sq = (t < 192) ? (d0*d0 + d1*d1 + d2*d2 + d3*d3) : 0.0f;
    float var = blockReduceSum256(sq, sm) * (1.0f / DIM);
    float r = rsqrtf(var + 1e-5f);
    if (t < 192) {
        const float4 wv = *(const float4*)(w + t * 4);
        const float4 bv = *(const float4*)(b + t * 4);
        __half2 h0 = __floats2half2_rn(d0 * r * wv.x + bv.x, d1 * r * wv.y + bv.y);
        __half2 h1 = __floats2half2_rn(d2 * r * wv.z + bv.z, d3 * r * wv.w + bv.w);
        __half2* orow = (__half2*)(o + (size_t)blockIdx.x * DIM);
        orow[t * 2]     = h0;
        orow[t * 2 + 1] = h1;
    }
}

__global__ void __launch_bounds__(256) zero_kernel(float* __restrict__ p, int n) {
    int i = blockIdx.x * 256 + threadIdx.x;
    if (i < n) p[i] = 0.0f;
}

__global__ void __launch_bounds__(256) half_copy_kernel(
    const float* __restrict__ in, __half* __restrict__ o, int n)
{
    int i = blockIdx.x * 256 + threadIdx.x;
    if (i < n) o[i] = __float2half_rn(in[i]);
}

// pad phase_w [64,768] -> [128,768] with zeros, fp16
__global__ void __launch_bounds__(256) pad_phw_kernel(
    const float* __restrict__ w, __half* __restrict__ o)
{
    int i = blockIdx.x * 256 + threadIdx.x;
    if (i < PDPAD * DIM) o[i] = __float2half_rn((i < PDIM * DIM) ? w[i] : 0.0f);
}

// transpose per batch: in [SEQ][DIM] -> out [DIM][SEQ]  (fp16)
__global__ void __launch_bounds__(256) transpose_kernel(
    const __half* __restrict__ in, __half* __restrict__ out)
{
    __shared__ __half t[32][33];
    int b = blockIdx.z;
    const __half* ib = in + (size_t)b * SEQ * DIM;
    __half* ob = out + (size_t)b * SEQ * DIM;
    int tx = threadIdx.x & 31, ty = threadIdx.x >> 5;
    int sbase = blockIdx.x * 32;
    int dbase = blockIdx.y * 32;
#pragma unroll
    for (int i = 0; i < 32; i += 8)
        t[ty + i][tx] = ib[(size_t)(sbase + ty + i) * DIM + dbase + tx];
    __syncthreads();
#pragma unroll
    for (int i = 0; i < 32; i += 8)
        ob[(size_t)(dbase + ty + i) * SEQ + sbase + tx] = t[tx][ty + i];
}

// ============================================================================
// fp16 tensor-core GEMM: 128x128x32 CTA tile, 8 warps (2x4), warp 64x32,
// mma.sync m16n8k16 (f32 accum), 4-stage cp.async pipeline, ldmatrix.x4.
// A [M,K] half row-major, B [N,K] half row-major: C = A @ B^T.
// EPI: 1=+bias->h, 2=tanh->h, 3=bias+GELU->h, 4=bias+residual->f,
//      5=row-divide(rowsum)+residual->f, 6=ex2(scale*v)->h (streaming store)
//        + atomic rowsum (scale pre-multiplied by log2e),
//      7=ex2(a2l*v + a2l)->h, a2l=0.5*alpha*log2e
// ============================================================================
template<int EPI> struct OutT { using T = __half; };
template<> struct OutT<4> { using T = float; };
template<> struct OutT<5> { using T = float; };

template<int EPI>
__global__ void __launch_bounds__(256, 2) tgemm(
    const __half* __restrict__ A, const __half* __restrict__ Bm,
    typename OutT<EPI>::T* __restrict__ C,
    int M, int N, int K, int lda, int ldb, int ldc,
    int zdiv,
    long as1, long as2, long bs1, long bs2, long cs1, long cs2,
    float scale,
    const float* __restrict__ bias,
    const float* __restrict__ res, long ress1,
    const float* __restrict__ rsum, long rsums1,
    const float* __restrict__ alphap,
    float* __restrict__ ssum)
{
    constexpr bool OUTH = (EPI != 4 && EPI != 5);
    extern __shared__ char sh[];

    int z = blockIdx.z;
    int z1 = z / zdiv, z2 = z - z1 * zdiv;
    A  += z1 * as1 + z2 * as2;
    Bm += z1 * bs1 + z2 * bs2;
    C  += z1 * cs1 + z2 * cs2;
    if (EPI == 4 || EPI == 5) res  += z1 * ress1;
    if (EPI == 5)             rsum += z1 * rsums1;
    if (EPI == 6)             ssum += (size_t)z * M;

    int tid  = threadIdx.x;
    int lane = tid & 31;
    int wid  = tid >> 5;
    int wm   = (wid & 1) * 64;
    int wn   = (wid >> 1) * 32;
    int g    = lane >> 2;
    int tg   = lane & 3;
    int bm = blockIdx.x * 128, bn = blockIdx.y * 128;

    float acc[4][4][4];
#pragma unroll
    for (int i = 0; i < 4; i++)
#pragma unroll
        for (int j = 0; j < 4; j++)
#pragma unroll
            for (int r = 0; r < 4; r++) acc[i][j][r] = 0.0f;

    // cp.async staging: thread -> row tid/2, 2x16B at half-col (tid&1)*16
    int r0 = tid >> 1;
    int hc = (tid & 1) << 4;                 // 0 or 16 halves
    unsigned base = smem_u32(sh);
    unsigned aDst = base + (unsigned)r0 * (LDRH * 2) + hc * 2;
    unsigned bDst = aDst + OPSTG;
    const __half* aSrc = A + (size_t)(bm + r0) * lda + hc;
    const __half* bSrc = Bm + (size_t)(bn + r0) * ldb + hc;

    // ldmatrix per-lane addresses (stage 0, ks 0); b16 8x8 rows = 16B
    int mi = lane >> 3, lr = lane & 7;
    unsigned aAddr[4], bAddr[2];
#pragma unroll
    for (int mt = 0; mt < 4; mt++)
        aAddr[mt] = base + (unsigned)(wm + mt * 16 + (mi & 1) * 8 + lr) * (LDRH * 2)
                  + (mi >> 1) * 16;
#pragma unroll
    for (int p = 0; p < 2; p++)
        bAddr[p] = base + OPSTG
                 + (unsigned)(wn + (p * 2 + (mi >> 1)) * 8 + lr) * (LDRH * 2)
                 + (mi & 1) * 16;

    auto stage_load = [&](int t, int T) {
        if (t < T) {
            unsigned so = (unsigned)(t % STAGES) * STAGE_BYTES;
            int k0 = t * BKH;
            cp_async16(aDst + so,      aSrc + k0);
            cp_async16(aDst + so + 16, aSrc + k0 + 8);
            cp_async16(bDst + so,      bSrc + k0);
            cp_async16(bDst + so + 16, bSrc + k0 + 8);
        }
        asm volatile("cp.async.commit_group;");
    };

    int T = K / BKH;
    stage_load(0, T);
    stage_load(1, T);
    stage_load(2, T);

    int s = 0;
    for (int t = 0; t < T; t++) {
        asm volatile("cp.async.wait_group 2;");
        __syncthreads();
        stage_load(t + 3, T);

        unsigned so = (unsigned)s * STAGE_BYTES;
#pragma unroll
        for (int ks = 0; ks < 2; ks++) {
            unsigned kofs = so + ks * 32;    // 16 halves per k16 step
            unsigned afr[4][4], bfr[4][2];
#pragma unroll
            for (int mt = 0; mt < 4; mt++)
                ldsm_x4(afr[mt][0], afr[mt][1], afr[mt][2], afr[mt][3],
                        aAddr[mt] + kofs);
            ldsm_x4(bfr[0][0], bfr[0][1], bfr[1][0], bfr[1][1], bAddr[0] + kofs);
            ldsm_x4(bfr[2][0], bfr[2][1], bfr[3][0], bfr[3][1], bAddr[1] + kofs);
#pragma unroll
            for (int mt = 0; mt < 4; mt++)
#pragma unroll
                for (int nt = 0; nt < 4; nt++)
                    mma_f16(acc[mt][nt], afr[mt], bfr[nt]);
        }
        if (++s >= STAGES) s = 0;
    }

    // ---------------- epilogue ----------------
    float a2v = 0.0f;
    if (EPI == 7) a2v = 0.5f * (*alphap) * LOG2E;

#pragma unroll
    for (int mt = 0; mt < 4; mt++) {
#pragma unroll
        for (int half = 0; half < 2; half++) {
            int m = bm + wm + mt * 16 + g + half * 8;
            float rinv = 0.0f;
            if (EPI == 5) rinv = 1.0f / rsum[m];
            float rs = 0.0f;
#pragma unroll
            for (int nt = 0; nt < 4; nt++) {
                int c = bn + wn + nt * 8 + tg * 2;
                float v0 = acc[mt][nt][half * 2];
                float v1 = acc[mt][nt][half * 2 + 1];
                if (EPI == 1) { v0 += bias[c]; v1 += bias[c + 1]; }
                if (EPI == 2) { v0 = tanhf(v0); v1 = tanhf(v1); }
                if (EPI == 3) {
                    v0 += bias[c]; v1 += bias[c + 1];
                    v0 = 0.5f * v0 * (1.0f + erff(v0 * 0.70710678118654752f));
                    v1 = 0.5f * v1 * (1.0f + erff(v1 * 0.70710678118654752f));
                }
                if (EPI == 4) {
                    const float2 rr = *(const float2*)(res + (size_t)m * ldc + c);
                    v0 += bias[c] + rr.x; v1 += bias[c + 1] + rr.y;
                }
                if (EPI == 5) {
                    const float2 rr = *(const float2*)(res + (size_t)m * ldc + c);
                    v0 = v0 * rinv + rr.x; v1 = v1 * rinv + rr.y;
                }
                if (EPI == 6) { v0 = ex2f(v0 * scale); v1 = ex2f(v1 * scale); rs += v0 + v1; }
                if (EPI == 7) { v0 = ex2f(fmaf(v0, a2v, a2v)); v1 = ex2f(fmaf(v1, a2v, a2v)); }
                if constexpr (OUTH) {
                    __half2 hv = __floats2half2_rn(v0, v1);
                    if (EPI == 6)
                        __stcs((__half2*)(C + (size_t)m * ldc + c), hv);  // streaming
                    else
                        *(__half2*)(C + (size_t)m * ldc + c) = hv;
                } else {
                    float2 o; o.x = v0; o.y = v1;
                    *(float2*)(C + (size_t)m * ldc + c) = o;
                }
            }
            if (EPI == 6) {
                rs += __shfl_xor_sync(0xffffffffu, rs, 1);
                rs += __shfl_xor_sync(0xffffffffu, rs, 2);
                if (tg == 0) atomicAdd(&ssum[m], rs);
            }
        }
    }
}

// --------- blend: u = (mean_h softmax_h + 1e-6) * pcexp; rowsum --------------
// 256 threads x 8 cols = 2048 = SEQ: exactly one vector iteration per thread.
// Streaming loads: scores/pc are read exactly once.
__global__ void __launch_bounds__(256) blend_kernel(
    const __half* __restrict__ scoresE, const float* __restrict__ ssum,
    const __half* __restrict__ pcexp, __half* __restrict__ blend,
    float* __restrict__ rowsum)
{
    __shared__ float sm[8];
    __shared__ float sinvl[NH];
    int b = blockIdx.x / SEQ;
    int i = blockIdx.x - b * SEQ;
    if (threadIdx.x < NH)
        sinvl[threadIdx.x] = 1.0f / (ssum[(b * NH + threadIdx.x) * SEQ + i] * (float)NH);
    __syncthreads();

    int j = threadIdx.x * 8;
    const __half* ebase = scoresE + (((size_t)(b * NH)) * SEQ + i) * SEQ + j;
    float w[8];
#pragma unroll
    for (int q = 0; q < 8; q++) w[q] = 1e-6f;
#pragma unroll
    for (int h = 0; h < NH; h++) {
        uint4 ev = __ldcs((const uint4*)(ebase + (size_t)h * SEQ * SEQ));
        const __half2* eh = (const __half2*)&ev;
        float sl = sinvl[h];
#pragma unroll
        for (int q = 0; q < 4; q++) {
            float2 f = __half22float2(eh[q]);
            w[2*q]   = fmaf(f.x, sl, w[2*q]);
            w[2*q+1] = fmaf(f.y, sl, w[2*q+1]);
        }
    }
    uint4 pv = __ldcs((const uint4*)(pcexp + ((size_t)b * SEQ + i) * SEQ + j));
    const __half2* ph = (const __half2*)&pv;
    __half2 ov[4];
    float lsum = 0.0f;
#pragma unroll
    for (int q = 0; q < 4; q++) {
        float2 p = __half22float2(ph[q]);
        float u0 = w[2*q] * p.x, u1 = w[2*q+1] * p.y;
        ov[q] = __floats2half2_rn(u0, u1);
        lsum += u0 + u1;
    }
    *(uint4*)(blend + ((size_t)b * SEQ + i) * SEQ + j) = *(uint4*)ov;
    lsum = blockReduceSum256(lsum, sm);
    if (threadIdx.x == 0) rowsum[blockIdx.x] = lsum;
}

// ---------------------------------------------------------------------------
extern "C" void kernel_launch(void* const* d_in, const int* in_sizes, int n_in,
                              void* d_out, int out_size)
{
    const float* x        = (const float*)d_in[0];
    const float* ln1_w    = (const float*)d_in[1];
    const float* ln1_b    = (const float*)d_in[2];
    const float* in_w     = (const float*)d_in[3];
    const float* in_b     = (const float*)d_in[4];
    const float* phase_w  = (const float*)d_in[5];
    const float* alpha    = (const float*)d_in[6];
    const float* ff_w1    = (const float*)d_in[7];
    const float* ff_b1    = (const float*)d_in[8];
    const float* ff_w2    = (const float*)d_in[9];
    const float* ff_b2    = (const float*)d_in[10];
    const float* ln2_w    = (const float*)d_in[11];
    const float* ln2_b    = (const float*)d_in[12];
    float* out            = (float*)d_out;

    __half *xn, *xnT, *qk, *phw, *phase, *scores, *pcv, *blend, *x2, *hbuf,
           *inw, *w1, *w2;
    float *ssum, *rowsum, *xmid;
    cudaGetSymbolAddress((void**)&xn,     g_xn);
    cudaGetSymbolAddress((void**)&xnT,    g_xnT);
    cudaGetSymbolAddress((void**)&qk,     g_qk);
    cudaGetSymbolAddress((void**)&phw,    g_phw);
    cudaGetSymbolAddress((void**)&phase,  g_phase);
    cudaGetSymbolAddress((void**)&scores, g_scores);
    cudaGetSymbolAddress((void**)&ssum,   g_ssum);
    cudaGetSymbolAddress((void**)&pcv,    g_pc);
    cudaGetSymbolAddress((void**)&blend,  g_blend);
    cudaGetSymbolAddress((void**)&rowsum, g_rowsum);
    cudaGetSymbolAddress((void**)&xmid,   g_xmid);
    cudaGetSymbolAddress((void**)&x2,     g_x2);
    cudaGetSymbolAddress((void**)&hbuf,   g_hbuf);
    cudaGetSymbolAddress((void**)&inw,    g_inw);
    cudaGetSymbolAddress((void**)&w1,     g_w1);
    cudaGetSymbolAddress((void**)&w2,     g_w2);

    cudaFuncSetAttribute(tgemm<1>, cudaFuncAttributeMaxDynamicSharedMemorySize, SMEM_DYN);
    cudaFuncSetAttribute(tgemm<2>, cudaFuncAttributeMaxDynamicSharedMemorySize, SMEM_DYN);
    cudaFuncSetAttribute(tgemm<3>, cudaFuncAttributeMaxDynamicSharedMemorySize, SMEM_DYN);
    cudaFuncSetAttribute(tgemm<4>, cudaFuncAttributeMaxDynamicSharedMemorySize, SMEM_DYN);
    cudaFuncSetAttribute(tgemm<5>, cudaFuncAttributeMaxDynamicSharedMemorySize, SMEM_DYN);
    cudaFuncSetAttribute(tgemm<6>, cudaFuncAttributeMaxDynamicSharedMemorySize, SMEM_DYN);
    cudaFuncSetAttribute(tgemm<7>, cudaFuncAttributeMaxDynamicSharedMemorySize, SMEM_DYN);

    // 0) fp16 round-to-nearest weight copies
    half_copy_kernel<<<(2*DIM*DIM + 255)/256, 256>>>(in_w, inw, 2*DIM*DIM);
    half_copy_kernel<<<(FFD*DIM + 255)/256, 256>>>(ff_w1, w1, FFD*DIM);
    half_copy_kernel<<<(DIM*FFD + 255)/256, 256>>>(ff_w2, w2, DIM*FFD);

    // 1) xn = LN1(x) -> fp16; xnT; zero per-head sums; pad+round phase_w
    ln_kernel<<<NROW, 256>>>(x, ln1_w, ln1_b, xn);
    zero_kernel<<<(BB*NH*SEQ + 255)/256, 256>>>(ssum, BB*NH*SEQ);
    pad_phw_kernel<<<(PDPAD*DIM + 255)/256, 256>>>(phase_w, phw);
    transpose_kernel<<<dim3(SEQ/32, DIM/32, BB), 256>>>(xn, xnT);

    // 2) qk = xn @ W[0:1536]^T + b -> fp16   [4096, 1536]
    tgemm<1><<<dim3(NROW/128, 1536/128, 1), 256, SMEM_DYN>>>(
        xn, inw, qk, NROW, 2*DIM, DIM, DIM, DIM, 2*DIM,
        1, 0,0, 0,0, 0,0, 1.0f, in_b, nullptr, 0, nullptr, 0, nullptr, nullptr);

    // 3) phase = tanh(xn @ phw^T) -> fp16    [4096, 128] (cols 64..127 = 0)
    tgemm<2><<<dim3(NROW/128, 1, 1), 256, SMEM_DYN>>>(
        xn, phw, phase, NROW, PDPAD, DIM, DIM, DIM, PDPAD,
        1, 0,0, 0,0, 0,0, 1.0f, nullptr, nullptr, 0, nullptr, 0, nullptr, nullptr);

    // 4) scores e = ex2(log2e/8 * q@k^T) -> fp16 (streaming) + rowsums
    tgemm<6><<<dim3(SEQ/128, SEQ/128, BB*NH), 256, SMEM_DYN>>>(
        qk, qk + DIM, scores, SEQ, SEQ, DHD, 2*DIM, 2*DIM, SEQ,
        NH, (long)SEQ*2*DIM, (long)DHD, (long)SEQ*2*DIM, (long)DHD,
            (long)NH*SEQ*SEQ, (long)SEQ*SEQ,
        0.125f * LOG2E, nullptr, nullptr, 0, nullptr, 0, nullptr, ssum);

    // 5) pcexp = ex2(a2l*(phase@phase^T) + a2l) -> fp16  2x[2048,2048], K=64
    tgemm<7><<<dim3(SEQ/128, SEQ/128, BB), 256, SMEM_DYN>>>(
        phase, phase, pcv, SEQ, SEQ, PDIM, PDPAD, PDPAD, SEQ,
        1, (long)SEQ*PDPAD, 0, (long)SEQ*PDPAD, 0, (long)SEQ*SEQ, 0,
        1.0f, nullptr, nullptr, 0, nullptr, 0, alpha, nullptr);

    // 6) blend weights (fp16) + row sums
    blend_kernel<<<BB*SEQ, 256>>>(scores, ssum, pcv, blend, rowsum);

    // 7) xmid = x + (blend/rowsum) @ xnT^T -> fp32   2x[2048, 768], K=2048
    tgemm<5><<<dim3(SEQ/128, DIM/128, BB), 256, SMEM_DYN>>>(
        blend, xnT, xmid, SEQ, DIM, SEQ, SEQ, SEQ, DIM,
        1, (long)SEQ*SEQ, 0, (long)DIM*SEQ, 0, (long)SEQ*DIM, 0,
        1.0f, nullptr, x, (long)SEQ*DIM, rowsum, (long)SEQ, nullptr, nullptr);

    // 8) x2 = LN2(xmid) -> fp16
    ln_kernel<<<NROW, 256>>>(xmid, ln2_w, ln2_b, x2);

    // 9) h = gelu(x2 @ ff_w1^T + b1) -> fp16  [4096, 3072]
    tgemm<3><<<dim3(NROW/128, FFD/128, 1), 256, SMEM_DYN>>>(
        x2, w1, hbuf, NROW, FFD, DIM, DIM, DIM, FFD,
        1, 0,0, 0,0, 0,0, 1.0f, ff_b1, nullptr, 0, nullptr, 0, nullptr, nullptr);

    // 10) out = xmid + h @ ff_w2^T + b2 -> fp32  [4096, 768], K=3072
    tgemm<4><<<dim3(NROW/128, DIM/128, 1), 256, SMEM_DYN>>>(
        hbuf, w2, out, NROW, DIM, FFD, FFD, FFD, DIM,
        1, 0,0, 0,0, 0,0, 1.0f, ff_b2, xmid, 0, nullptr, 0, nullptr, nullptr);

    (void)in_sizes; (void)n_in; (void)out_size;
}

// round 15
// speedup vs baseline: 1.0739x; 1.0148x over previous
#include <cuda_runtime.h>
#include <cuda_fp16.h>
#include <math.h>

// Problem dims (fixed by the reference)
#define BB   2
#define SEQ  2048
#define DIM  768
#define NH   12
#define DHD  64
#define FFD  3072
#define PDIM 64
#define PDPAD 128
#define NROW (BB*SEQ)      // 4096

#define STAGES 4
#define BKH    32                        // k-tile in halves
#define LDRH   40                        // padded row length in halves (80 B)
#define OPSTG  (128*LDRH*2)              // 10240 B per operand per stage
#define STAGE_BYTES (2*OPSTG)            // 20480
#define SMEM_DYN (STAGES*STAGE_BYTES)    // 81920

#define LOG2E 1.4426950408889634f

// ---------------- scratch (device globals; no cudaMalloc allowed) ----------
__device__ __align__(16) __half g_xn[NROW*DIM];
__device__ __align__(16) __half g_xnT[NROW*DIM];                  // [B][D][S]
__device__ __align__(16) __half g_qk[NROW*2*DIM];
__device__ __align__(16) __half g_phw[PDPAD*DIM];
__device__ __align__(16) __half g_phase[NROW*PDPAD];
__device__              float  g_ssum[BB*NH*SEQ];
__device__ __align__(16) __half g_scores[(size_t)BB*NH*SEQ*SEQ]; // exp(s/8) fp16
__device__ __align__(16) __half g_pc[(size_t)BB*SEQ*SEQ];        // exp(a*(pc+1)/2)
__device__ __align__(16) __half g_blend[(size_t)BB*SEQ*SEQ];
__device__              float  g_rowsum[BB*SEQ];
__device__ __align__(16) float  g_xmid[NROW*DIM];                // residual: fp32
__device__ __align__(16) __half g_x2[NROW*DIM];
__device__ __align__(16) __half g_hbuf[NROW*FFD];
// fp16-rounded weight copies
__device__ __align__(16) __half g_inw[2*DIM*DIM];
__device__ __align__(16) __half g_w1[FFD*DIM];
__device__ __align__(16) __half g_w2[DIM*FFD];

// ---------------- helpers ----------------------------------------------------
__device__ __forceinline__ float warpReduceSum(float v) {
#pragma unroll
    for (int o = 16; o > 0; o >>= 1) v += __shfl_xor_sync(0xffffffffu, v, o);
    return v;
}
__device__ __forceinline__ float blockReduceSum256(float v, float* sm) {
    v = warpReduceSum(v);
    if ((threadIdx.x & 31) == 0) sm[threadIdx.x >> 5] = v;
    __syncthreads();
    if (threadIdx.x < 32) {
        float t = (threadIdx.x < 8) ? sm[threadIdx.x] : 0.0f;
        t = warpReduceSum(t);
        if (threadIdx.x == 0) sm[0] = t;
    }
    __syncthreads();
    float r = sm[0];
    __syncthreads();
    return r;
}

// exp via MUFU EX2: x assumed scaled by LOG2E already. rel err ~2.4e-7.
__device__ __forceinline__ float ex2f(float x) {
    float r;
    asm("ex2.approx.f32 %0, %1;" : "=f"(r) : "f"(x));
    return r;
}

__device__ __forceinline__ unsigned smem_u32(const void* p) {
    unsigned a;
    asm("{ .reg .u64 t; cvta.to.shared.u64 t, %1; cvt.u32.u64 %0, t; }"
        : "=r"(a) : "l"(p));
    return a;
}
__device__ __forceinline__ void cp_async16(unsigned dst, const void* src) {
    asm volatile("cp.async.cg.shared.global [%0], [%1], 16;" :: "r"(dst), "l"(src));
}
__device__ __forceinline__ void ldsm_x4(unsigned& r0, unsigned& r1,
                                        unsigned& r2, unsigned& r3, unsigned addr) {
    asm volatile("ldmatrix.sync.aligned.m8n8.x4.shared.b16 {%0,%1,%2,%3}, [%4];"
        : "=r"(r0), "=r"(r1), "=r"(r2), "=r"(r3) : "r"(addr));
}
__device__ __forceinline__ void mma_f16(float* c, const unsigned* a, const unsigned* b) {
    asm("mma.sync.aligned.m16n8k16.row.col.f32.f16.f16.f32 "
        "{%0,%1,%2,%3}, {%4,%5,%6,%7}, {%8,%9}, {%0,%1,%2,%3};"
        : "+f"(c[0]), "+f"(c[1]), "+f"(c[2]), "+f"(c[3])
        : "r"(a[0]), "r"(a[1]), "r"(a[2]), "r"(a[3]), "r"(b[0]), "r"(b[1]));
}

// ---------------- LayerNorm: warp-per-row, no barriers -----------------------
// 256 threads = 8 warps = 8 rows per block; lane holds 24 elements (6 float4).
__global__ void __launch_bounds__(256) ln_kernel(
    const float* __restrict__ x, const float* __restrict__ w,
    const float* __restrict__ b, __half* __restrict__ o)
{
    int wid = threadIdx.x >> 5, lane = threadIdx.x & 31;
    size_t row = (size_t)blockIdx.x * 8 + wid;
    const float* xr = x + row * DIM;

    float4 v[6];
    float s = 0.0f;
#pragma unroll
    for (int k = 0; k < 6; k++) {
        v[k] = *(const float4*)(xr + lane * 4 + k * 128);
        s += v[k].x + v[k].y + v[k].z + v[k].w;
    }
    float mean = warpReduceSum(s) * (1.0f / DIM);
    float sq = 0.0f;
#pragma unroll
    for (int k = 0; k < 6; k++) {
        v[k].x -= mean; v[k].y -= mean; v[k].z -= mean; v[k].w -= mean;
        sq += v[k].x*v[k].x + v[k].y*v[k].y + v[k].z*v[k].z + v[k].w*v[k].w;
    }
    float r = rsqrtf(warpReduceSum(sq) * (1.0f / DIM) + 1e-5f);
    __half* orow = o + row * DIM;
#pragma unroll
    for (int k = 0; k < 6; k++) {
        int c = lane * 4 + k * 128;
        const float4 wv = *(const float4*)(w + c);
        const float4 bv = *(const float4*)(b + c);
        __half2 h0 = __floats2half2_rn(v[k].x * r * wv.x + bv.x,
                                       v[k].y * r * wv.y + bv.y);
        __half2 h1 = __floats2half2_rn(v[k].z * r * wv.z + bv.z,
                                       v[k].w * r * wv.w + bv.w);
        *(__half2*)(orow + c)     = h0;
        *(__half2*)(orow + c + 2) = h1;
    }
}

__global__ void __launch_bounds__(256) zero_kernel(float* __restrict__ p, int n) {
    int i = blockIdx.x * 256 + threadIdx.x;
    if (i < n) p[i] = 0.0f;
}

__global__ void __launch_bounds__(256) half_copy_kernel(
    const float* __restrict__ in, __half* __restrict__ o, int n)
{
    int i = blockIdx.x * 256 + threadIdx.x;
    if (i < n) o[i] = __float2half_rn(in[i]);
}

// pad phase_w [64,768] -> [128,768] with zeros (fp16); also zero ssum
__global__ void __launch_bounds__(256) pad_phw_kernel(
    const float* __restrict__ w, __half* __restrict__ o, float* __restrict__ ssum)
{
    int i = blockIdx.x * 256 + threadIdx.x;
    if (i < PDPAD * DIM) o[i] = __float2half_rn((i < PDIM * DIM) ? w[i] : 0.0f);
    if (i < BB * NH * SEQ) ssum[i] = 0.0f;
}

// transpose per batch: in [SEQ][DIM] -> out [DIM][SEQ]  (fp16)
__global__ void __launch_bounds__(256) transpose_kernel(
    const __half* __restrict__ in, __half* __restrict__ out)
{
    __shared__ __half t[32][33];
    int b = blockIdx.z;
    const __half* ib = in + (size_t)b * SEQ * DIM;
    __half* ob = out + (size_t)b * SEQ * DIM;
    int tx = threadIdx.x & 31, ty = threadIdx.x >> 5;
    int sbase = blockIdx.x * 32;
    int dbase = blockIdx.y * 32;
#pragma unroll
    for (int i = 0; i < 32; i += 8)
        t[ty + i][tx] = ib[(size_t)(sbase + ty + i) * DIM + dbase + tx];
    __syncthreads();
#pragma unroll
    for (int i = 0; i < 32; i += 8)
        ob[(size_t)(dbase + ty + i) * SEQ + sbase + tx] = t[tx][ty + i];
}

// ============================================================================
// fp16 tensor-core GEMM: 128x128x32 CTA tile, 8 warps (2x4), warp 64x32,
// mma.sync m16n8k16 (f32 accum), 4-stage cp.async pipeline, ldmatrix.x4.
// A [M,K] half row-major, B [N,K] half row-major: C = A @ B^T.
// EPI: 1=+bias->h, 2=tanh->h, 3=bias+GELU->h, 4=bias+residual->f,
//      5=row-divide(rowsum)+residual->f, 6=ex2(scale*v)->h (streaming store)
//        + atomic rowsum (scale pre-multiplied by log2e),
//      7=ex2(a2l*v + a2l)->h, a2l=0.5*alpha*log2e
// ============================================================================
template<int EPI> struct OutT { using T = __half; };
template<> struct OutT<4> { using T = float; };
template<> struct OutT<5> { using T = float; };

template<int EPI>
__global__ void __launch_bounds__(256, 2) tgemm(
    const __half* __restrict__ A, const __half* __restrict__ Bm,
    typename OutT<EPI>::T* __restrict__ C,
    int M, int N, int K, int lda, int ldb, int ldc,
    int zdiv,
    long as1, long as2, long bs1, long bs2, long cs1, long cs2,
    float scale,
    const float* __restrict__ bias,
    const float* __restrict__ res, long ress1,
    const float* __restrict__ rsum, long rsums1,
    const float* __restrict__ alphap,
    float* __restrict__ ssum)
{
    constexpr bool OUTH = (EPI != 4 && EPI != 5);
    extern __shared__ char sh[];

    int z = blockIdx.z;
    int z1 = z / zdiv, z2 = z - z1 * zdiv;
    A  += z1 * as1 + z2 * as2;
    Bm += z1 * bs1 + z2 * bs2;
    C  += z1 * cs1 + z2 * cs2;
    if (EPI == 4 || EPI == 5) res  += z1 * ress1;
    if (EPI == 5)             rsum += z1 * rsums1;
    if (EPI == 6)             ssum += (size_t)z * M;

    int tid  = threadIdx.x;
    int lane = tid & 31;
    int wid  = tid >> 5;
    int wm   = (wid & 1) * 64;
    int wn   = (wid >> 1) * 32;
    int g    = lane >> 2;
    int tg   = lane & 3;
    int bm = blockIdx.x * 128, bn = blockIdx.y * 128;

    float acc[4][4][4];
#pragma unroll
    for (int i = 0; i < 4; i++)
#pragma unroll
        for (int j = 0; j < 4; j++)
#pragma unroll
            for (int r = 0; r < 4; r++) acc[i][j][r] = 0.0f;

    // cp.async staging: thread -> row tid/2, 2x16B at half-col (tid&1)*16
    int r0 = tid >> 1;
    int hc = (tid & 1) << 4;                 // 0 or 16 halves
    unsigned base = smem_u32(sh);
    unsigned aDst = base + (unsigned)r0 * (LDRH * 2) + hc * 2;
    unsigned bDst = aDst + OPSTG;
    const __half* aSrc = A + (size_t)(bm + r0) * lda + hc;
    const __half* bSrc = Bm + (size_t)(bn + r0) * ldb + hc;

    // ldmatrix per-lane addresses (stage 0, ks 0); b16 8x8 rows = 16B
    int mi = lane >> 3, lr = lane & 7;
    unsigned aAddr[4], bAddr[2];
#pragma unroll
    for (int mt = 0; mt < 4; mt++)
        aAddr[mt] = base + (unsigned)(wm + mt * 16 + (mi & 1) * 8 + lr) * (LDRH * 2)
                  + (mi >> 1) * 16;
#pragma unroll
    for (int p = 0; p < 2; p++)
        bAddr[p] = base + OPSTG
                 + (unsigned)(wn + (p * 2 + (mi >> 1)) * 8 + lr) * (LDRH * 2)
                 + (mi & 1) * 16;

    auto stage_load = [&](int t, int T) {
        if (t < T) {
            unsigned so = (unsigned)(t % STAGES) * STAGE_BYTES;
            int k0 = t * BKH;
            cp_async16(aDst + so,      aSrc + k0);
            cp_async16(aDst + so + 16, aSrc + k0 + 8);
            cp_async16(bDst + so,      bSrc + k0);
            cp_async16(bDst + so + 16, bSrc + k0 + 8);
        }
        asm volatile("cp.async.commit_group;");
    };

    int T = K / BKH;
    stage_load(0, T);
    stage_load(1, T);
    stage_load(2, T);

    int s = 0;
    for (int t = 0; t < T; t++) {
        asm volatile("cp.async.wait_group 2;");
        __syncthreads();
        stage_load(t + 3, T);

        unsigned so = (unsigned)s * STAGE_BYTES;
#pragma unroll
        for (int ks = 0; ks < 2; ks++) {
            unsigned kofs = so + ks * 32;    // 16 halves per k16 step
            unsigned afr[4][4], bfr[4][2];
#pragma unroll
            for (int mt = 0; mt < 4; mt++)
                ldsm_x4(afr[mt][0], afr[mt][1], afr[mt][2], afr[mt][3],
                        aAddr[mt] + kofs);
            ldsm_x4(bfr[0][0], bfr[0][1], bfr[1][0], bfr[1][1], bAddr[0] + kofs);
            ldsm_x4(bfr[2][0], bfr[2][1], bfr[3][0], bfr[3][1], bAddr[1] + kofs);
#pragma unroll
            for (int mt = 0; mt < 4; mt++)
#pragma unroll
                for (int nt = 0; nt < 4; nt++)
                    mma_f16(acc[mt][nt], afr[mt], bfr[nt]);
        }
        if (++s >= STAGES) s = 0;
    }

    // ---------------- epilogue ----------------
    float a2v = 0.0f;
    if (EPI == 7) a2v = 0.5f * (*alphap) * LOG2E;

#pragma unroll
    for (int mt = 0; mt < 4; mt++) {
#pragma unroll
        for (int half = 0; half < 2; half++) {
            int m = bm + wm + mt * 16 + g + half * 8;
            float rinv = 0.0f;
            if (EPI == 5) rinv = 1.0f / rsum[m];
            float rs = 0.0f;
#pragma unroll
            for (int nt = 0; nt < 4; nt++) {
                int c = bn + wn + nt * 8 + tg * 2;
                float v0 = acc[mt][nt][half * 2];
                float v1 = acc[mt][nt][half * 2 + 1];
                if (EPI == 1) { v0 += bias[c]; v1 += bias[c + 1]; }
                if (EPI == 2) { v0 = tanhf(v0); v1 = tanhf(v1); }
                if (EPI == 3) {
                    v0 += bias[c]; v1 += bias[c + 1];
                    v0 = 0.5f * v0 * (1.0f + erff(v0 * 0.70710678118654752f));
                    v1 = 0.5f * v1 * (1.0f + erff(v1 * 0.70710678118654752f));
                }
                if (EPI == 4) {
                    const float2 rr = *(const float2*)(res + (size_t)m * ldc + c);
                    v0 += bias[c] + rr.x; v1 += bias[c + 1] + rr.y;
                }
                if (EPI == 5) {
                    const float2 rr = *(const float2*)(res + (size_t)m * ldc + c);
                    v0 = v0 * rinv + rr.x; v1 = v1 * rinv + rr.y;
                }
                if (EPI == 6) { v0 = ex2f(v0 * scale); v1 = ex2f(v1 * scale); rs += v0 + v1; }
                if (EPI == 7) { v0 = ex2f(fmaf(v0, a2v, a2v)); v1 = ex2f(fmaf(v1, a2v, a2v)); }
                if constexpr (OUTH) {
                    __half2 hv = __floats2half2_rn(v0, v1);
                    if (EPI == 6)
                        __stcs((__half2*)(C + (size_t)m * ldc + c), hv);  // streaming
                    else
                        *(__half2*)(C + (size_t)m * ldc + c) = hv;
                } else {
                    float2 o; o.x = v0; o.y = v1;
                    *(float2*)(C + (size_t)m * ldc + c) = o;
                }
            }
            if (EPI == 6) {
                rs += __shfl_xor_sync(0xffffffffu, rs, 1);
                rs += __shfl_xor_sync(0xffffffffu, rs, 2);
                if (tg == 0) atomicAdd(&ssum[m], rs);
            }
        }
    }
}

// --------- blend: u = (mean_h softmax_h + 1e-6) * pcexp; rowsum --------------
// 256 threads x 8 cols = 2048 = SEQ: exactly one vector iteration per thread.
// Streaming loads: scores/pc are read exactly once.
__global__ void __launch_bounds__(256) blend_kernel(
    const __half* __restrict__ scoresE, const float* __restrict__ ssum,
    const __half* __restrict__ pcexp, __half* __restrict__ blend,
    float* __restrict__ rowsum)
{
    __shared__ float sm[8];
    __shared__ float sinvl[NH];
    int b = blockIdx.x / SEQ;
    int i = blockIdx.x - b * SEQ;
    if (threadIdx.x < NH)
        sinvl[threadIdx.x] = 1.0f / (ssum[(b * NH + threadIdx.x) * SEQ + i] * (float)NH);
    __syncthreads();

    int j = threadIdx.x * 8;
    const __half* ebase = scoresE + (((size_t)(b * NH)) * SEQ + i) * SEQ + j;
    float w[8];
#pragma unroll
    for (int q = 0; q < 8; q++) w[q] = 1e-6f;
#pragma unroll
    for (int h = 0; h < NH; h++) {
        uint4 ev = __ldcs((const uint4*)(ebase + (size_t)h * SEQ * SEQ));
        const __half2* eh = (const __half2*)&ev;
        float sl = sinvl[h];
#pragma unroll
        for (int q = 0; q < 4; q++) {
            float2 f = __half22float2(eh[q]);
            w[2*q]   = fmaf(f.x, sl, w[2*q]);
            w[2*q+1] = fmaf(f.y, sl, w[2*q+1]);
        }
    }
    uint4 pv = __ldcs((const uint4*)(pcexp + ((size_t)b * SEQ + i) * SEQ + j));
    const __half2* ph = (const __half2*)&pv;
    __half2 ov[4];
    float lsum = 0.0f;
#pragma unroll
    for (int q = 0; q < 4; q++) {
        float2 p = __half22float2(ph[q]);
        float u0 = w[2*q] * p.x, u1 = w[2*q+1] * p.y;
        ov[q] = __floats2half2_rn(u0, u1);
        lsum += u0 + u1;
    }
    *(uint4*)(blend + ((size_t)b * SEQ + i) * SEQ + j) = *(uint4*)ov;
    lsum = blockReduceSum256(lsum, sm);
    if (threadIdx.x == 0) rowsum[blockIdx.x] = lsum;
}

// ---------------------------------------------------------------------------
extern "C" void kernel_launch(void* const* d_in, const int* in_sizes, int n_in,
                              void* d_out, int out_size)
{
    const float* x        = (const float*)d_in[0];
    const float* ln1_w    = (const float*)d_in[1];
    const float* ln1_b    = (const float*)d_in[2];
    const float* in_w     = (const float*)d_in[3];
    const float* in_b     = (const float*)d_in[4];
    const float* phase_w  = (const float*)d_in[5];
    const float* alpha    = (const float*)d_in[6];
    const float* ff_w1    = (const float*)d_in[7];
    const float* ff_b1    = (const float*)d_in[8];
    const float* ff_w2    = (const float*)d_in[9];
    const float* ff_b2    = (const float*)d_in[10];
    const float* ln2_w    = (const float*)d_in[11];
    const float* ln2_b    = (const float*)d_in[12];
    float* out            = (float*)d_out;

    __half *xn, *xnT, *qk, *phw, *phase, *scores, *pcv, *blend, *x2, *hbuf,
           *inw, *w1, *w2;
    float *ssum, *rowsum, *xmid;
    cudaGetSymbolAddress((void**)&xn,     g_xn);
    cudaGetSymbolAddress((void**)&xnT,    g_xnT);
    cudaGetSymbolAddress((void**)&qk,     g_qk);
    cudaGetSymbolAddress((void**)&phw,    g_phw);
    cudaGetSymbolAddress((void**)&phase,  g_phase);
    cudaGetSymbolAddress((void**)&scores, g_scores);
    cudaGetSymbolAddress((void**)&ssum,   g_ssum);
    cudaGetSymbolAddress((void**)&pcv,    g_pc);
    cudaGetSymbolAddress((void**)&blend,  g_blend);
    cudaGetSymbolAddress((void**)&rowsum, g_rowsum);
    cudaGetSymbolAddress((void**)&xmid,   g_xmid);
    cudaGetSymbolAddress((void**)&x2,     g_x2);
    cudaGetSymbolAddress((void**)&hbuf,   g_hbuf);
    cudaGetSymbolAddress((void**)&inw,    g_inw);
    cudaGetSymbolAddress((void**)&w1,     g_w1);
    cudaGetSymbolAddress((void**)&w2,     g_w2);

    cudaFuncSetAttribute(tgemm<1>, cudaFuncAttributeMaxDynamicSharedMemorySize, SMEM_DYN);
    cudaFuncSetAttribute(tgemm<2>, cudaFuncAttributeMaxDynamicSharedMemorySize, SMEM_DYN);
    cudaFuncSetAttribute(tgemm<3>, cudaFuncAttributeMaxDynamicSharedMemorySize, SMEM_DYN);
    cudaFuncSetAttribute(tgemm<4>, cudaFuncAttributeMaxDynamicSharedMemorySize, SMEM_DYN);
    cudaFuncSetAttribute(tgemm<5>, cudaFuncAttributeMaxDynamicSharedMemorySize, SMEM_DYN);
    cudaFuncSetAttribute(tgemm<6>, cudaFuncAttributeMaxDynamicSharedMemorySize, SMEM_DYN);
    cudaFuncSetAttribute(tgemm<7>, cudaFuncAttributeMaxDynamicSharedMemorySize, SMEM_DYN);

    // 0) fp16 round-to-nearest weight copies
    half_copy_kernel<<<(2*DIM*DIM + 255)/256, 256>>>(in_w, inw, 2*DIM*DIM);
    half_copy_kernel<<<(FFD*DIM + 255)/256, 256>>>(ff_w1, w1, FFD*DIM);
    half_copy_kernel<<<(DIM*FFD + 255)/256, 256>>>(ff_w2, w2, DIM*FFD);

    // 1) xn = LN1(x) -> fp16 (warp-per-row); xnT; pad+round phase_w + zero ssum
    ln_kernel<<<NROW/8, 256>>>(x, ln1_w, ln1_b, xn);
    pad_phw_kernel<<<(PDPAD*DIM + 255)/256, 256>>>(phase_w, phw, ssum);
    transpose_kernel<<<dim3(SEQ/32, DIM/32, BB), 256>>>(xn, xnT);

    // 2) qk = xn @ W[0:1536]^T + b -> fp16   [4096, 1536]
    tgemm<1><<<dim3(NROW/128, 1536/128, 1), 256, SMEM_DYN>>>(
        xn, inw, qk, NROW, 2*DIM, DIM, DIM, DIM, 2*DIM,
        1, 0,0, 0,0, 0,0, 1.0f, in_b, nullptr, 0, nullptr, 0, nullptr, nullptr);

    // 3) phase = tanh(xn @ phw^T) -> fp16    [4096, 128] (cols 64..127 = 0)
    tgemm<2><<<dim3(NROW/128, 1, 1), 256, SMEM_DYN>>>(
        xn, phw, phase, NROW, PDPAD, DIM, DIM, DIM, PDPAD,
        1, 0,0, 0,0, 0,0, 1.0f, nullptr, nullptr, 0, nullptr, 0, nullptr, nullptr);

    // 4) scores e = ex2(log2e/8 * q@k^T) -> fp16 (streaming) + rowsums
    tgemm<6><<<dim3(SEQ/128, SEQ/128, BB*NH), 256, SMEM_DYN>>>(
        qk, qk + DIM, scores, SEQ, SEQ, DHD, 2*DIM, 2*DIM, SEQ,
        NH, (long)SEQ*2*DIM, (long)DHD, (long)SEQ*2*DIM, (long)DHD,
            (long)NH*SEQ*SEQ, (long)SEQ*SEQ,
        0.125f * LOG2E, nullptr, nullptr, 0, nullptr, 0, nullptr, ssum);

    // 5) pcexp = ex2(a2l*(phase@phase^T) + a2l) -> fp16  2x[2048,2048], K=64
    tgemm<7><<<dim3(SEQ/128, SEQ/128, BB), 256, SMEM_DYN>>>(
        phase, phase, pcv, SEQ, SEQ, PDIM, PDPAD, PDPAD, SEQ,
        1, (long)SEQ*PDPAD, 0, (long)SEQ*PDPAD, 0, (long)SEQ*SEQ, 0,
        1.0f, nullptr, nullptr, 0, nullptr, 0, alpha, nullptr);

    // 6) blend weights (fp16) + row sums
    blend_kernel<<<BB*SEQ, 256>>>(scores, ssum, pcv, blend, rowsum);

    // 7) xmid = x + (blend/rowsum) @ xnT^T -> fp32   2x[2048, 768], K=2048
    tgemm<5><<<dim3(SEQ/128, DIM/128, BB), 256, SMEM_DYN>>>(
        blend, xnT, xmid, SEQ, DIM, SEQ, SEQ, SEQ, DIM,
        1, (long)SEQ*SEQ, 0, (long)DIM*SEQ, 0, (long)SEQ*DIM, 0,
        1.0f, nullptr, x, (long)SEQ*DIM, rowsum, (long)SEQ, nullptr, nullptr);

    // 8) x2 = LN2(xmid) -> fp16 (warp-per-row)
    ln_kernel<<<NROW/8, 256>>>(xmid, ln2_w, ln2_b, x2);

    // 9) h = gelu(x2 @ ff_w1^T + b1) -> fp16  [4096, 3072]
    tgemm<3><<<dim3(NROW/128, FFD/128, 1), 256, SMEM_DYN>>>(
        x2, w1, hbuf, NROW, FFD, DIM, DIM, DIM, FFD,
        1, 0,0, 0,0, 0,0, 1.0f, ff_b1, nullptr, 0, nullptr, 0, nullptr, nullptr);

    // 10) out = xmid + h @ ff_w2^T + b2 -> fp32  [4096, 768], K=3072
    tgemm<4><<<dim3(NROW/128, DIM/128, 1), 256, SMEM_DYN>>>(
        hbuf, w2, out, NROW, DIM, FFD, FFD, FFD, DIM,
        1, 0,0, 0,0, 0,0, 1.0f, ff_b2, xmid, 0, nullptr, 0, nullptr, nullptr);

    (void)in_sizes; (void)n_in; (void)out_size;
}

// round 16
// speedup vs baseline: 1.0940x; 1.0188x over previous
#include <cuda_runtime.h>
#include <cuda_fp16.h>
#include <math.h>

// Problem dims (fixed by the reference)
#define BB   2
#define SEQ  2048
#define DIM  768
#define NH   12
#define DHD  64
#define FFD  3072
#define PDIM 64
#define PDPAD 128
#define NROW (BB*SEQ)      // 4096

#define STAGES 4
#define BKH    32                        // k-tile in halves
#define LDRH   40                        // padded row length in halves (80 B)
#define OPSTG  (128*LDRH*2)              // 10240 B per operand per stage
#define STAGE_BYTES (2*OPSTG)            // 20480
#define SMEM_DYN (STAGES*STAGE_BYTES)    // 81920

#define LOG2E 1.4426950408889634f

// ---------------- scratch (device globals; no cudaMalloc allowed) ----------
__device__ __align__(16) __half g_xn[NROW*DIM];
__device__ __align__(16) __half g_xnT[NROW*DIM];                  // [B][D][S]
__device__ __align__(16) __half g_qk[NROW*2*DIM];
__device__ __align__(16) __half g_phw[PDPAD*DIM];
__device__ __align__(16) __half g_phase[NROW*PDPAD];
__device__              float  g_ssum[BB*NH*SEQ];
__device__ __align__(16) __half g_scores[(size_t)BB*NH*SEQ*SEQ]; // exp(s/8) fp16
__device__ __align__(16) __half g_pc[(size_t)BB*SEQ*SEQ];        // exp(a*(pc+1)/2)
__device__ __align__(16) __half g_blend[(size_t)BB*SEQ*SEQ];
__device__              float  g_rowsum[BB*SEQ];
__device__ __align__(16) float  g_xmid[NROW*DIM];                // residual: fp32
__device__ __align__(16) __half g_x2[NROW*DIM];
__device__ __align__(16) __half g_hbuf[NROW*FFD];
// fp16-rounded weight copies
__device__ __align__(16) __half g_inw[2*DIM*DIM];
__device__ __align__(16) __half g_w1[FFD*DIM];
__device__ __align__(16) __half g_w2[DIM*FFD];

// ---------------- helpers ----------------------------------------------------
__device__ __forceinline__ float warpReduceSum(float v) {
#pragma unroll
    for (int o = 16; o > 0; o >>= 1) v += __shfl_xor_sync(0xffffffffu, v, o);
    return v;
}
__device__ __forceinline__ float blockReduceSum256(float v, float* sm) {
    v = warpReduceSum(v);
    if ((threadIdx.x & 31) == 0) sm[threadIdx.x >> 5] = v;
    __syncthreads();
    if (threadIdx.x < 32) {
        float t = (threadIdx.x < 8) ? sm[threadIdx.x] : 0.0f;
        t = warpReduceSum(t);
        if (threadIdx.x == 0) sm[0] = t;
    }
    __syncthreads();
    float r = sm[0];
    __syncthreads();
    return r;
}

// exp via MUFU EX2: x assumed scaled by LOG2E already. rel err ~2.4e-7.
__device__ __forceinline__ float ex2f(float x) {
    float r;
    asm("ex2.approx.f32 %0, %1;" : "=f"(r) : "f"(x));
    return r;
}

__device__ __forceinline__ unsigned smem_u32(const void* p) {
    unsigned a;
    asm("{ .reg .u64 t; cvta.to.shared.u64 t, %1; cvt.u32.u64 %0, t; }"
        : "=r"(a) : "l"(p));
    return a;
}
__device__ __forceinline__ void cp_async16(unsigned dst, const void* src) {
    asm volatile("cp.async.cg.shared.global [%0], [%1], 16;" :: "r"(dst), "l"(src));
}
__device__ __forceinline__ void ldsm_x4(unsigned& r0, unsigned& r1,
                                        unsigned& r2, unsigned& r3, unsigned addr) {
    asm volatile("ldmatrix.sync.aligned.m8n8.x4.shared.b16 {%0,%1,%2,%3}, [%4];"
        : "=r"(r0), "=r"(r1), "=r"(r2), "=r"(r3) : "r"(addr));
}
__device__ __forceinline__ void mma_f16(float* c, const unsigned* a, const unsigned* b) {
    asm("mma.sync.aligned.m16n8k16.row.col.f32.f16.f16.f32 "
        "{%0,%1,%2,%3}, {%4,%5,%6,%7}, {%8,%9}, {%0,%1,%2,%3};"
        : "+f"(c[0]), "+f"(c[1]), "+f"(c[2]), "+f"(c[3])
        : "r"(a[0]), "r"(a[1]), "r"(a[2]), "r"(a[3]), "r"(b[0]), "r"(b[1]));
}

// ---------------- LayerNorm: warp-per-row, no barriers -----------------------
// 256 threads = 8 warps = 8 rows per block; lane holds 24 elements (6 float4).
__global__ void __launch_bounds__(256) ln_kernel(
    const float* __restrict__ x, const float* __restrict__ w,
    const float* __restrict__ b, __half* __restrict__ o)
{
    int wid = threadIdx.x >> 5, lane = threadIdx.x & 31;
    size_t row = (size_t)blockIdx.x * 8 + wid;
    const float* xr = x + row * DIM;

    float4 v[6];
    float s = 0.0f;
#pragma unroll
    for (int k = 0; k < 6; k++) {
        v[k] = *(const float4*)(xr + lane * 4 + k * 128);
        s += v[k].x + v[k].y + v[k].z + v[k].w;
    }
    float mean = warpReduceSum(s) * (1.0f / DIM);
    float sq = 0.0f;
#pragma unroll
    for (int k = 0; k < 6; k++) {
        v[k].x -= mean; v[k].y -= mean; v[k].z -= mean; v[k].w -= mean;
        sq += v[k].x*v[k].x + v[k].y*v[k].y + v[k].z*v[k].z + v[k].w*v[k].w;
    }
    float r = rsqrtf(warpReduceSum(sq) * (1.0f / DIM) + 1e-5f);
    __half* orow = o + row * DIM;
#pragma unroll
    for (int k = 0; k < 6; k++) {
        int c = lane * 4 + k * 128;
        const float4 wv = *(const float4*)(w + c);
        const float4 bv = *(const float4*)(b + c);
        __half2 h0 = __floats2half2_rn(v[k].x * r * wv.x + bv.x,
                                       v[k].y * r * wv.y + bv.y);
        __half2 h1 = __floats2half2_rn(v[k].z * r * wv.z + bv.z,
                                       v[k].w * r * wv.w + bv.w);
        *(__half2*)(orow + c)     = h0;
        *(__half2*)(orow + c + 2) = h1;
    }
}

// ---------------- prep: all fp16 weight copies + pad + ssum zero in ONE pass -
// grid strided over the largest array (w1/w2: FFD*DIM elements).
__global__ void __launch_bounds__(256) prep_kernel(
    const float* __restrict__ in_w, __half* __restrict__ inw,
    const float* __restrict__ ff_w1, __half* __restrict__ w1,
    const float* __restrict__ ff_w2, __half* __restrict__ w2,
    const float* __restrict__ phase_w, __half* __restrict__ phw,
    float* __restrict__ ssum)
{
    int i = blockIdx.x * 256 + threadIdx.x;
    if (i < FFD * DIM) {
        w1[i] = __float2half_rn(ff_w1[i]);
        w2[i] = __float2half_rn(ff_w2[i]);
    }
    if (i < 2 * DIM * DIM) inw[i] = __float2half_rn(in_w[i]);
    if (i < PDPAD * DIM)
        phw[i] = __float2half_rn((i < PDIM * DIM) ? phase_w[i] : 0.0f);
    if (i < BB * NH * SEQ) ssum[i] = 0.0f;
}

// transpose per batch: in [SEQ][DIM] -> out [DIM][SEQ]  (fp16)
__global__ void __launch_bounds__(256) transpose_kernel(
    const __half* __restrict__ in, __half* __restrict__ out)
{
    __shared__ __half t[32][33];
    int b = blockIdx.z;
    const __half* ib = in + (size_t)b * SEQ * DIM;
    __half* ob = out + (size_t)b * SEQ * DIM;
    int tx = threadIdx.x & 31, ty = threadIdx.x >> 5;
    int sbase = blockIdx.x * 32;
    int dbase = blockIdx.y * 32;
#pragma unroll
    for (int i = 0; i < 32; i += 8)
        t[ty + i][tx] = ib[(size_t)(sbase + ty + i) * DIM + dbase + tx];
    __syncthreads();
#pragma unroll
    for (int i = 0; i < 32; i += 8)
        ob[(size_t)(dbase + ty + i) * SEQ + sbase + tx] = t[tx][ty + i];
}

// ============================================================================
// fp16 tensor-core GEMM: 128x128x32 CTA tile, 8 warps (2x4), warp 64x32,
// mma.sync m16n8k16 (f32 accum), 4-stage cp.async pipeline, ldmatrix.x4.
// A [M,K] half row-major, B [N,K] half row-major: C = A @ B^T.
// EPI: 1=+bias->h, 2=tanh->h, 3=bias+GELU->h, 4=bias+residual->f,
//      5=row-divide(rowsum)+residual->f, 6=ex2(scale*v)->h (streaming store)
//        + atomic rowsum (scale pre-multiplied by log2e),
//      7=ex2(a2l*v + a2l)->h, a2l=0.5*alpha*log2e
// ============================================================================
template<int EPI> struct OutT { using T = __half; };
template<> struct OutT<4> { using T = float; };
template<> struct OutT<5> { using T = float; };

template<int EPI>
__global__ void __launch_bounds__(256, 2) tgemm(
    const __half* __restrict__ A, const __half* __restrict__ Bm,
    typename OutT<EPI>::T* __restrict__ C,
    int M, int N, int K, int lda, int ldb, int ldc,
    int zdiv,
    long as1, long as2, long bs1, long bs2, long cs1, long cs2,
    float scale,
    const float* __restrict__ bias,
    const float* __restrict__ res, long ress1,
    const float* __restrict__ rsum, long rsums1,
    const float* __restrict__ alphap,
    float* __restrict__ ssum)
{
    constexpr bool OUTH = (EPI != 4 && EPI != 5);
    extern __shared__ char sh[];

    int z = blockIdx.z;
    int z1 = z / zdiv, z2 = z - z1 * zdiv;
    A  += z1 * as1 + z2 * as2;
    Bm += z1 * bs1 + z2 * bs2;
    C  += z1 * cs1 + z2 * cs2;
    if (EPI == 4 || EPI == 5) res  += z1 * ress1;
    if (EPI == 5)             rsum += z1 * rsums1;
    if (EPI == 6)             ssum += (size_t)z * M;

    int tid  = threadIdx.x;
    int lane = tid & 31;
    int wid  = tid >> 5;
    int wm   = (wid & 1) * 64;
    int wn   = (wid >> 1) * 32;
    int g    = lane >> 2;
    int tg   = lane & 3;
    int bm = blockIdx.x * 128, bn = blockIdx.y * 128;

    float acc[4][4][4];
#pragma unroll
    for (int i = 0; i < 4; i++)
#pragma unroll
        for (int j = 0; j < 4; j++)
#pragma unroll
            for (int r = 0; r < 4; r++) acc[i][j][r] = 0.0f;

    // cp.async staging: thread -> row tid/2, 2x16B at half-col (tid&1)*16
    int r0 = tid >> 1;
    int hc = (tid & 1) << 4;                 // 0 or 16 halves
    unsigned base = smem_u32(sh);
    unsigned aDst = base + (unsigned)r0 * (LDRH * 2) + hc * 2;
    unsigned bDst = aDst + OPSTG;
    const __half* aSrc = A + (size_t)(bm + r0) * lda + hc;
    const __half* bSrc = Bm + (size_t)(bn + r0) * ldb + hc;

    // ldmatrix per-lane addresses (stage 0, ks 0); b16 8x8 rows = 16B
    int mi = lane >> 3, lr = lane & 7;
    unsigned aAddr[4], bAddr[2];
#pragma unroll
    for (int mt = 0; mt < 4; mt++)
        aAddr[mt] = base + (unsigned)(wm + mt * 16 + (mi & 1) * 8 + lr) * (LDRH * 2)
                  + (mi >> 1) * 16;
#pragma unroll
    for (int p = 0; p < 2; p++)
        bAddr[p] = base + OPSTG
                 + (unsigned)(wn + (p * 2 + (mi >> 1)) * 8 + lr) * (LDRH * 2)
                 + (mi & 1) * 16;

    auto stage_load = [&](int t, int T) {
        if (t < T) {
            unsigned so = (unsigned)(t % STAGES) * STAGE_BYTES;
            int k0 = t * BKH;
            cp_async16(aDst + so,      aSrc + k0);
            cp_async16(aDst + so + 16, aSrc + k0 + 8);
            cp_async16(bDst + so,      bSrc + k0);
            cp_async16(bDst + so + 16, bSrc + k0 + 8);
        }
        asm volatile("cp.async.commit_group;");
    };

    int T = K / BKH;
    stage_load(0, T);
    stage_load(1, T);
    stage_load(2, T);

    int s = 0;
    for (int t = 0; t < T; t++) {
        asm volatile("cp.async.wait_group 2;");
        __syncthreads();
        stage_load(t + 3, T);

        unsigned so = (unsigned)s * STAGE_BYTES;
#pragma unroll
        for (int ks = 0; ks < 2; ks++) {
            unsigned kofs = so + ks * 32;    // 16 halves per k16 step
            unsigned afr[4][4], bfr[4][2];
#pragma unroll
            for (int mt = 0; mt < 4; mt++)
                ldsm_x4(afr[mt][0], afr[mt][1], afr[mt][2], afr[mt][3],
                        aAddr[mt] + kofs);
            ldsm_x4(bfr[0][0], bfr[0][1], bfr[1][0], bfr[1][1], bAddr[0] + kofs);
            ldsm_x4(bfr[2][0], bfr[2][1], bfr[3][0], bfr[3][1], bAddr[1] + kofs);
#pragma unroll
            for (int mt = 0; mt < 4; mt++)
#pragma unroll
                for (int nt = 0; nt < 4; nt++)
                    mma_f16(acc[mt][nt], afr[mt], bfr[nt]);
        }
        if (++s >= STAGES) s = 0;
    }

    // ---------------- epilogue ----------------
    float a2v = 0.0f;
    if (EPI == 7) a2v = 0.5f * (*alphap) * LOG2E;

#pragma unroll
    for (int mt = 0; mt < 4; mt++) {
#pragma unroll
        for (int half = 0; half < 2; half++) {
            int m = bm + wm + mt * 16 + g + half * 8;
            float rinv = 0.0f;
            if (EPI == 5) rinv = 1.0f / rsum[m];
            float rs = 0.0f;
#pragma unroll
            for (int nt = 0; nt < 4; nt++) {
                int c = bn + wn + nt * 8 + tg * 2;
                float v0 = acc[mt][nt][half * 2];
                float v1 = acc[mt][nt][half * 2 + 1];
                if (EPI == 1) { v0 += bias[c]; v1 += bias[c + 1]; }
                if (EPI == 2) { v0 = tanhf(v0); v1 = tanhf(v1); }
                if (EPI == 3) {
                    v0 += bias[c]; v1 += bias[c + 1];
                    v0 = 0.5f * v0 * (1.0f + erff(v0 * 0.70710678118654752f));
                    v1 = 0.5f * v1 * (1.0f + erff(v1 * 0.70710678118654752f));
                }
                if (EPI == 4) {
                    const float2 rr = *(const float2*)(res + (size_t)m * ldc + c);
                    v0 += bias[c] + rr.x; v1 += bias[c + 1] + rr.y;
                }
                if (EPI == 5) {
                    const float2 rr = *(const float2*)(res + (size_t)m * ldc + c);
                    v0 = v0 * rinv + rr.x; v1 = v1 * rinv + rr.y;
                }
                if (EPI == 6) { v0 = ex2f(v0 * scale); v1 = ex2f(v1 * scale); rs += v0 + v1; }
                if (EPI == 7) { v0 = ex2f(fmaf(v0, a2v, a2v)); v1 = ex2f(fmaf(v1, a2v, a2v)); }
                if constexpr (OUTH) {
                    __half2 hv = __floats2half2_rn(v0, v1);
                    if (EPI == 6)
                        __stcs((__half2*)(C + (size_t)m * ldc + c), hv);  // streaming
                    else
                        *(__half2*)(C + (size_t)m * ldc + c) = hv;
                } else {
                    float2 o; o.x = v0; o.y = v1;
                    *(float2*)(C + (size_t)m * ldc + c) = o;
                }
            }
            if (EPI == 6) {
                rs += __shfl_xor_sync(0xffffffffu, rs, 1);
                rs += __shfl_xor_sync(0xffffffffu, rs, 2);
                if (tg == 0) atomicAdd(&ssum[m], rs);
            }
        }
    }
}

// --------- blend: u = (mean_h softmax_h + 1e-6) * pcexp; rowsum --------------
// 256 threads x 8 cols = 2048 = SEQ: exactly one vector iteration per thread.
// Streaming loads: scores/pc are read exactly once.
__global__ void __launch_bounds__(256) blend_kernel(
    const __half* __restrict__ scoresE, const float* __restrict__ ssum,
    const __half* __restrict__ pcexp, __half* __restrict__ blend,
    float* __restrict__ rowsum)
{
    __shared__ float sm[8];
    __shared__ float sinvl[NH];
    int b = blockIdx.x / SEQ;
    int i = blockIdx.x - b * SEQ;
    if (threadIdx.x < NH)
        sinvl[threadIdx.x] = 1.0f / (ssum[(b * NH + threadIdx.x) * SEQ + i] * (float)NH);
    __syncthreads();

    int j = threadIdx.x * 8;
    const __half* ebase = scoresE + (((size_t)(b * NH)) * SEQ + i) * SEQ + j;
    float w[8];
#pragma unroll
    for (int q = 0; q < 8; q++) w[q] = 1e-6f;
#pragma unroll
    for (int h = 0; h < NH; h++) {
        uint4 ev = __ldcs((const uint4*)(ebase + (size_t)h * SEQ * SEQ));
        const __half2* eh = (const __half2*)&ev;
        float sl = sinvl[h];
#pragma unroll
        for (int q = 0; q < 4; q++) {
            float2 f = __half22float2(eh[q]);
            w[2*q]   = fmaf(f.x, sl, w[2*q]);
            w[2*q+1] = fmaf(f.y, sl, w[2*q+1]);
        }
    }
    uint4 pv = __ldcs((const uint4*)(pcexp + ((size_t)b * SEQ + i) * SEQ + j));
    const __half2* ph = (const __half2*)&pv;
    __half2 ov[4];
    float lsum = 0.0f;
#pragma unroll
    for (int q = 0; q < 4; q++) {
        float2 p = __half22float2(ph[q]);
        float u0 = w[2*q] * p.x, u1 = w[2*q+1] * p.y;
        ov[q] = __floats2half2_rn(u0, u1);
        lsum += u0 + u1;
    }
    *(uint4*)(blend + ((size_t)b * SEQ + i) * SEQ + j) = *(uint4*)ov;
    lsum = blockReduceSum256(lsum, sm);
    if (threadIdx.x == 0) rowsum[blockIdx.x] = lsum;
}

// ---------------------------------------------------------------------------
extern "C" void kernel_launch(void* const* d_in, const int* in_sizes, int n_in,
                              void* d_out, int out_size)
{
    const float* x        = (const float*)d_in[0];
    const float* ln1_w    = (const float*)d_in[1];
    const float* ln1_b    = (const float*)d_in[2];
    const float* in_w     = (const float*)d_in[3];
    const float* in_b     = (const float*)d_in[4];
    const float* phase_w  = (const float*)d_in[5];
    const float* alpha    = (const float*)d_in[6];
    const float* ff_w1    = (const float*)d_in[7];
    const float* ff_b1    = (const float*)d_in[8];
    const float* ff_w2    = (const float*)d_in[9];
    const float* ff_b2    = (const float*)d_in[10];
    const float* ln2_w    = (const float*)d_in[11];
    const float* ln2_b    = (const float*)d_in[12];
    float* out            = (float*)d_out;

    __half *xn, *xnT, *qk, *phw, *phase, *scores, *pcv, *blend, *x2, *hbuf,
           *inw, *w1, *w2;
    float *ssum, *rowsum, *xmid;
    cudaGetSymbolAddress((void**)&xn,     g_xn);
    cudaGetSymbolAddress((void**)&xnT,    g_xnT);
    cudaGetSymbolAddress((void**)&qk,     g_qk);
    cudaGetSymbolAddress((void**)&phw,    g_phw);
    cudaGetSymbolAddress((void**)&phase,  g_phase);
    cudaGetSymbolAddress((void**)&scores, g_scores);
    cudaGetSymbolAddress((void**)&ssum,   g_ssum);
    cudaGetSymbolAddress((void**)&pcv,    g_pc);
    cudaGetSymbolAddress((void**)&blend,  g_blend);
    cudaGetSymbolAddress((void**)&rowsum, g_rowsum);
    cudaGetSymbolAddress((void**)&xmid,   g_xmid);
    cudaGetSymbolAddress((void**)&x2,     g_x2);
    cudaGetSymbolAddress((void**)&hbuf,   g_hbuf);
    cudaGetSymbolAddress((void**)&inw,    g_inw);
    cudaGetSymbolAddress((void**)&w1,     g_w1);
    cudaGetSymbolAddress((void**)&w2,     g_w2);

    cudaFuncSetAttribute(tgemm<1>, cudaFuncAttributeMaxDynamicSharedMemorySize, SMEM_DYN);
    cudaFuncSetAttribute(tgemm<2>, cudaFuncAttributeMaxDynamicSharedMemorySize, SMEM_DYN);
    cudaFuncSetAttribute(tgemm<3>, cudaFuncAttributeMaxDynamicSharedMemorySize, SMEM_DYN);
    cudaFuncSetAttribute(tgemm<4>, cudaFuncAttributeMaxDynamicSharedMemorySize, SMEM_DYN);
    cudaFuncSetAttribute(tgemm<5>, cudaFuncAttributeMaxDynamicSharedMemorySize, SMEM_DYN);
    cudaFuncSetAttribute(tgemm<6>, cudaFuncAttributeMaxDynamicSharedMemorySize, SMEM_DYN);
    cudaFuncSetAttribute(tgemm<7>, cudaFuncAttributeMaxDynamicSharedMemorySize, SMEM_DYN);

    // 0) all weight rounding + padding + ssum zero in ONE kernel
    prep_kernel<<<(FFD*DIM + 255)/256, 256>>>(
        in_w, inw, ff_w1, w1, ff_w2, w2, phase_w, phw, ssum);

    // 1) xn = LN1(x) -> fp16 (warp-per-row); xnT
    ln_kernel<<<NROW/8, 256>>>(x, ln1_w, ln1_b, xn);
    transpose_kernel<<<dim3(SEQ/32, DIM/32, BB), 256>>>(xn, xnT);

    // 2) qk = xn @ W[0:1536]^T + b -> fp16   [4096, 1536]
    tgemm<1><<<dim3(NROW/128, 1536/128, 1), 256, SMEM_DYN>>>(
        xn, inw, qk, NROW, 2*DIM, DIM, DIM, DIM, 2*DIM,
        1, 0,0, 0,0, 0,0, 1.0f, in_b, nullptr, 0, nullptr, 0, nullptr, nullptr);

    // 3) phase = tanh(xn @ phw^T) -> fp16    [4096, 128] (cols 64..127 = 0)
    tgemm<2><<<dim3(NROW/128, 1, 1), 256, SMEM_DYN>>>(
        xn, phw, phase, NROW, PDPAD, DIM, DIM, DIM, PDPAD,
        1, 0,0, 0,0, 0,0, 1.0f, nullptr, nullptr, 0, nullptr, 0, nullptr, nullptr);

    // 4) scores e = ex2(log2e/8 * q@k^T) -> fp16 (streaming) + rowsums
    tgemm<6><<<dim3(SEQ/128, SEQ/128, BB*NH), 256, SMEM_DYN>>>(
        qk, qk + DIM, scores, SEQ, SEQ, DHD, 2*DIM, 2*DIM, SEQ,
        NH, (long)SEQ*2*DIM, (long)DHD, (long)SEQ*2*DIM, (long)DHD,
            (long)NH*SEQ*SEQ, (long)SEQ*SEQ,
        0.125f * LOG2E, nullptr, nullptr, 0, nullptr, 0, nullptr, ssum);

    // 5) pcexp = ex2(a2l*(phase@phase^T) + a2l) -> fp16  2x[2048,2048], K=64
    tgemm<7><<<dim3(SEQ/128, SEQ/128, BB), 256, SMEM_DYN>>>(
        phase, phase, pcv, SEQ, SEQ, PDIM, PDPAD, PDPAD, SEQ,
        1, (long)SEQ*PDPAD, 0, (long)SEQ*PDPAD, 0, (long)SEQ*SEQ, 0,
        1.0f, nullptr, nullptr, 0, nullptr, 0, alpha, nullptr);

    // 6) blend weights (fp16) + row sums
    blend_kernel<<<BB*SEQ, 256>>>(scores, ssum, pcv, blend, rowsum);

    // 7) xmid = x + (blend/rowsum) @ xnT^T -> fp32   2x[2048, 768], K=2048
    tgemm<5><<<dim3(SEQ/128, DIM/128, BB), 256, SMEM_DYN>>>(
        blend, xnT, xmid, SEQ, DIM, SEQ, SEQ, SEQ, DIM,
        1, (long)SEQ*SEQ, 0, (long)DIM*SEQ, 0, (long)SEQ*DIM, 0,
        1.0f, nullptr, x, (long)SEQ*DIM, rowsum, (long)SEQ, nullptr, nullptr);

    // 8) x2 = LN2(xmid) -> fp16 (warp-per-row)
    ln_kernel<<<NROW/8, 256>>>(xmid, ln2_w, ln2_b, x2);

    // 9) h = gelu(x2 @ ff_w1^T + b1) -> fp16  [4096, 3072]
    tgemm<3><<<dim3(NROW/128, FFD/128, 1), 256, SMEM_DYN>>>(
        x2, w1, hbuf, NROW, FFD, DIM, DIM, DIM, FFD,
        1, 0,0, 0,0, 0,0, 1.0f, ff_b1, nullptr, 0, nullptr, 0, nullptr, nullptr);

    // 10) out = xmid + h @ ff_w2^T + b2 -> fp32  [4096, 768], K=3072
    tgemm<4><<<dim3(NROW/128, DIM/128, 1), 256, SMEM_DYN>>>(
        hbuf, w2, out, NROW, DIM, FFD, FFD, FFD, DIM,
        1, 0,0, 0,0, 0,0, 1.0f, ff_b2, xmid, 0, nullptr, 0, nullptr, nullptr);

    (void)in_sizes; (void)n_in; (void)out_size;
}

// round 17
// speedup vs baseline: 1.0982x; 1.0038x over previous
#include <cuda_runtime.h>
#include <cuda_fp16.h>
#include <math.h>

// Problem dims (fixed by the reference)
#define BB   2
#define SEQ  2048
#define DIM  768
#define NH   12
#define DHD  64
#define FFD  3072
#define PDIM 64
#define PDPAD 128
#define NROW (BB*SEQ)      // 4096

#define STAGES 4
#define BKH    32                        // k-tile in halves
#define LDRH   40                        // padded row length in halves (80 B)
#define OPSTG  (128*LDRH*2)              // 10240 B : A operand per stage
#define SMEM_128 (STAGES*(OPSTG + 128*LDRH*2))   // 81920
#define SMEM_64  (STAGES*(OPSTG +  64*LDRH*2))   // 61440

#define LOG2E 1.4426950408889634f

// ---------------- scratch (device globals; no cudaMalloc allowed) ----------
__device__ __align__(16) __half g_xn[NROW*DIM];
__device__ __align__(16) __half g_xnT[NROW*DIM];                  // [B][D][S]
__device__ __align__(16) __half g_qk[NROW*2*DIM];
__device__ __align__(16) __half g_phw[PDPAD*DIM];
__device__ __align__(16) __half g_phase[NROW*PDPAD];
__device__              float  g_ssum[BB*NH*SEQ];
__device__ __align__(16) __half g_scores[(size_t)BB*NH*SEQ*SEQ]; // exp(s/8) fp16
__device__ __align__(16) __half g_pc[(size_t)BB*SEQ*SEQ];        // exp(a*(pc+1)/2)
__device__ __align__(16) __half g_blend[(size_t)BB*SEQ*SEQ];
__device__              float  g_rowsum[BB*SEQ];
__device__ __align__(16) float  g_xmid[NROW*DIM];                // residual: fp32
__device__ __align__(16) __half g_x2[NROW*DIM];
__device__ __align__(16) __half g_hbuf[NROW*FFD];
// fp16-rounded weight copies
__device__ __align__(16) __half g_inw[2*DIM*DIM];
__device__ __align__(16) __half g_w1[FFD*DIM];
__device__ __align__(16) __half g_w2[DIM*FFD];

// ---------------- helpers ----------------------------------------------------
__device__ __forceinline__ float warpReduceSum(float v) {
#pragma unroll
    for (int o = 16; o > 0; o >>= 1) v += __shfl_xor_sync(0xffffffffu, v, o);
    return v;
}
__device__ __forceinline__ float blockReduceSum256(float v, float* sm) {
    v = warpReduceSum(v);
    if ((threadIdx.x & 31) == 0) sm[threadIdx.x >> 5] = v;
    __syncthreads();
    if (threadIdx.x < 32) {
        float t = (threadIdx.x < 8) ? sm[threadIdx.x] : 0.0f;
        t = warpReduceSum(t);
        if (threadIdx.x == 0) sm[0] = t;
    }
    __syncthreads();
    float r = sm[0];
    __syncthreads();
    return r;
}

// exp via MUFU EX2: x assumed scaled by LOG2E already. rel err ~2.4e-7.
__device__ __forceinline__ float ex2f(float x) {
    float r;
    asm("ex2.approx.f32 %0, %1;" : "=f"(r) : "f"(x));
    return r;
}

__device__ __forceinline__ unsigned smem_u32(const void* p) {
    unsigned a;
    asm("{ .reg .u64 t; cvta.to.shared.u64 t, %1; cvt.u32.u64 %0, t; }"
        : "=r"(a) : "l"(p));
    return a;
}
__device__ __forceinline__ void cp_async16(unsigned dst, const void* src) {
    asm volatile("cp.async.cg.shared.global [%0], [%1], 16;" :: "r"(dst), "l"(src));
}
__device__ __forceinline__ void ldsm_x4(unsigned& r0, unsigned& r1,
                                        unsigned& r2, unsigned& r3, unsigned addr) {
    asm volatile("ldmatrix.sync.aligned.m8n8.x4.shared.b16 {%0,%1,%2,%3}, [%4];"
        : "=r"(r0), "=r"(r1), "=r"(r2), "=r"(r3) : "r"(addr));
}
__device__ __forceinline__ void mma_f16(float* c, const unsigned* a, const unsigned* b) {
    asm("mma.sync.aligned.m16n8k16.row.col.f32.f16.f16.f32 "
        "{%0,%1,%2,%3}, {%4,%5,%6,%7}, {%8,%9}, {%0,%1,%2,%3};"
        : "+f"(c[0]), "+f"(c[1]), "+f"(c[2]), "+f"(c[3])
        : "r"(a[0]), "r"(a[1]), "r"(a[2]), "r"(a[3]), "r"(b[0]), "r"(b[1]));
}

// ---------------- LayerNorm: warp-per-row, no barriers -----------------------
__global__ void __launch_bounds__(256) ln_kernel(
    const float* __restrict__ x, const float* __restrict__ w,
    const float* __restrict__ b, __half* __restrict__ o)
{
    int wid = threadIdx.x >> 5, lane = threadIdx.x & 31;
    size_t row = (size_t)blockIdx.x * 8 + wid;
    const float* xr = x + row * DIM;

    float4 v[6];
    float s = 0.0f;
#pragma unroll
    for (int k = 0; k < 6; k++) {
        v[k] = *(const float4*)(xr + lane * 4 + k * 128);
        s += v[k].x + v[k].y + v[k].z + v[k].w;
    }
    float mean = warpReduceSum(s) * (1.0f / DIM);
    float sq = 0.0f;
#pragma unroll
    for (int k = 0; k < 6; k++) {
        v[k].x -= mean; v[k].y -= mean; v[k].z -= mean; v[k].w -= mean;
        sq += v[k].x*v[k].x + v[k].y*v[k].y + v[k].z*v[k].z + v[k].w*v[k].w;
    }
    float r = rsqrtf(warpReduceSum(sq) * (1.0f / DIM) + 1e-5f);
    __half* orow = o + row * DIM;
#pragma unroll
    for (int k = 0; k < 6; k++) {
        int c = lane * 4 + k * 128;
        const float4 wv = *(const float4*)(w + c);
        const float4 bv = *(const float4*)(b + c);
        __half2 h0 = __floats2half2_rn(v[k].x * r * wv.x + bv.x,
                                       v[k].y * r * wv.y + bv.y);
        __half2 h1 = __floats2half2_rn(v[k].z * r * wv.z + bv.z,
                                       v[k].w * r * wv.w + bv.w);
        *(__half2*)(orow + c)     = h0;
        *(__half2*)(orow + c + 2) = h1;
    }
}

// ---------------- prep: weight copies + pad + ssum zero in ONE pass ---------
__global__ void __launch_bounds__(256) prep_kernel(
    const float* __restrict__ in_w, __half* __restrict__ inw,
    const float* __restrict__ ff_w1, __half* __restrict__ w1,
    const float* __restrict__ ff_w2, __half* __restrict__ w2,
    const float* __restrict__ phase_w, __half* __restrict__ phw,
    float* __restrict__ ssum)
{
    int i = blockIdx.x * 256 + threadIdx.x;
    if (i < FFD * DIM) {
        w1[i] = __float2half_rn(ff_w1[i]);
        w2[i] = __float2half_rn(ff_w2[i]);
    }
    if (i < 2 * DIM * DIM) inw[i] = __float2half_rn(in_w[i]);
    if (i < PDPAD * DIM)
        phw[i] = __float2half_rn((i < PDIM * DIM) ? phase_w[i] : 0.0f);
    if (i < BB * NH * SEQ) ssum[i] = 0.0f;
}

// transpose per batch: in [SEQ][DIM] -> out [DIM][SEQ]  (fp16)
__global__ void __launch_bounds__(256) transpose_kernel(
    const __half* __restrict__ in, __half* __restrict__ out)
{
    __shared__ __half t[32][33];
    int b = blockIdx.z;
    const __half* ib = in + (size_t)b * SEQ * DIM;
    __half* ob = out + (size_t)b * SEQ * DIM;
    int tx = threadIdx.x & 31, ty = threadIdx.x >> 5;
    int sbase = blockIdx.x * 32;
    int dbase = blockIdx.y * 32;
#pragma unroll
    for (int i = 0; i < 32; i += 8)
        t[ty + i][tx] = ib[(size_t)(sbase + ty + i) * DIM + dbase + tx];
    __syncthreads();
#pragma unroll
    for (int i = 0; i < 32; i += 8)
        ob[(size_t)(dbase + ty + i) * SEQ + sbase + tx] = t[tx][ty + i];
}

// ============================================================================
// fp16 tensor-core GEMM: 128xBN x32 CTA tile (BN=128 or 64), 8 warps,
// warp tile 64x(BN/4), mma.sync m16n8k16, 4-stage cp.async, ldmatrix.x4.
// A [M,K] half row-major, B [N,K] half row-major: C = A @ B^T.
// EPI: 1=+bias->h, 2=tanh->h, 3=bias+GELU->h, 4=bias+residual->f,
//      5=row-divide(rowsum)+residual->f, 6=ex2(scale*v)->h (streaming) + rowsum,
//      7=ex2(a2l*v + a2l)->h
// ============================================================================
template<int EPI> struct OutT { using T = __half; };
template<> struct OutT<4> { using T = float; };
template<> struct OutT<5> { using T = float; };

template<int EPI, int BN>
__global__ void __launch_bounds__(256, 2) tgemm(
    const __half* __restrict__ A, const __half* __restrict__ Bm,
    typename OutT<EPI>::T* __restrict__ C,
    int M, int N, int K, int lda, int ldb, int ldc,
    int zdiv,
    long as1, long as2, long bs1, long bs2, long cs1, long cs2,
    float scale,
    const float* __restrict__ bias,
    const float* __restrict__ res, long ress1,
    const float* __restrict__ rsum, long rsums1,
    const float* __restrict__ alphap,
    float* __restrict__ ssum)
{
    constexpr bool OUTH = (EPI != 4 && EPI != 5);
    constexpr int NT = BN / 32;               // MMA n-tiles per warp (4 or 2)
    constexpr unsigned BSTG = BN * LDRH * 2;  // B bytes per stage
    constexpr unsigned STG  = OPSTG + BSTG;   // stage stride
    constexpr int TPRB = 256 / BN;            // threads per B row (2 or 4)
    extern __shared__ char sh[];

    int z = blockIdx.z;
    int z1 = z / zdiv, z2 = z - z1 * zdiv;
    A  += z1 * as1 + z2 * as2;
    Bm += z1 * bs1 + z2 * bs2;
    C  += z1 * cs1 + z2 * cs2;
    if (EPI == 4 || EPI == 5) res  += z1 * ress1;
    if (EPI == 5)             rsum += z1 * rsums1;
    if (EPI == 6)             ssum += (size_t)z * M;

    int tid  = threadIdx.x;
    int lane = tid & 31;
    int wid  = tid >> 5;
    int wm   = (wid & 1) * 64;
    int wn   = (wid >> 1) * (BN / 4);
    int g    = lane >> 2;
    int tg   = lane & 3;
    int bm = blockIdx.x * 128, bn = blockIdx.y * BN;

    float acc[4][NT][4];
#pragma unroll
    for (int i = 0; i < 4; i++)
#pragma unroll
        for (int j = 0; j < NT; j++)
#pragma unroll
            for (int r = 0; r < 4; r++) acc[i][j][r] = 0.0f;

    // cp.async staging
    int r0 = tid >> 1;
    int hc = (tid & 1) << 4;                       // A: 2 thr/row, 16 halves each
    int rb = tid / TPRB;
    int cb = (tid % TPRB) * (32 / TPRB);           // B: 16 or 8 halves each
    unsigned base = smem_u32(sh);
    unsigned aDst = base + (unsigned)r0 * (LDRH * 2) + hc * 2;
    unsigned bDst = base + OPSTG + (unsigned)rb * (LDRH * 2) + cb * 2;
    const __half* aSrc = A + (size_t)(bm + r0) * lda + hc;
    const __half* bSrc = Bm + (size_t)(bn + rb) * ldb + cb;

    // ldmatrix per-lane addresses (stage 0, ks 0)
    int mi = lane >> 3, lr = lane & 7;
    unsigned aAddr[4], bAddr[NT / 2];
#pragma unroll
    for (int mt = 0; mt < 4; mt++)
        aAddr[mt] = base + (unsigned)(wm + mt * 16 + (mi & 1) * 8 + lr) * (LDRH * 2)
                  + (mi >> 1) * 16;
#pragma unroll
    for (int p = 0; p < NT / 2; p++)
        bAddr[p] = base + OPSTG
                 + (unsigned)(wn + (p * 2 + (mi >> 1)) * 8 + lr) * (LDRH * 2)
                 + (mi & 1) * 16;

    auto stage_load = [&](int t, int T) {
        if (t < T) {
            unsigned so = (unsigned)(t % STAGES) * STG;
            int k0 = t * BKH;
            cp_async16(aDst + so,      aSrc + k0);
            cp_async16(aDst + so + 16, aSrc + k0 + 8);
            cp_async16(bDst + so, bSrc + k0);
            if (BN == 128) cp_async16(bDst + so + 16, bSrc + k0 + 8);
        }
        asm volatile("cp.async.commit_group;");
    };

    int T = K / BKH;
    stage_load(0, T);
    stage_load(1, T);
    stage_load(2, T);

    int s = 0;
    for (int t = 0; t < T; t++) {
        asm volatile("cp.async.wait_group 2;");
        __syncthreads();
        stage_load(t + 3, T);

        unsigned so = (unsigned)s * STG;
#pragma unroll
        for (int ks = 0; ks < 2; ks++) {
            unsigned kofs = so + ks * 32;    // 16 halves per k16 step
            unsigned afr[4][4], bfr[NT][2];
#pragma unroll
            for (int mt = 0; mt < 4; mt++)
                ldsm_x4(afr[mt][0], afr[mt][1], afr[mt][2], afr[mt][3],
                        aAddr[mt] + kofs);
#pragma unroll
            for (int p = 0; p < NT / 2; p++)
                ldsm_x4(bfr[p*2][0], bfr[p*2][1], bfr[p*2+1][0], bfr[p*2+1][1],
                        bAddr[p] + kofs);
#pragma unroll
            for (int mt = 0; mt < 4; mt++)
#pragma unroll
                for (int nt = 0; nt < NT; nt++)
                    mma_f16(acc[mt][nt], afr[mt], bfr[nt]);
        }
        if (++s >= STAGES) s = 0;
    }

    // ---------------- epilogue ----------------
    float a2v = 0.0f;
    if (EPI == 7) a2v = 0.5f * (*alphap) * LOG2E;

#pragma unroll
    for (int mt = 0; mt < 4; mt++) {
#pragma unroll
        for (int half = 0; half < 2; half++) {
            int m = bm + wm + mt * 16 + g + half * 8;
            float rinv = 0.0f;
            if (EPI == 5) rinv = 1.0f / rsum[m];
            float rs = 0.0f;
#pragma unroll
            for (int nt = 0; nt < NT; nt++) {
                int c = bn + wn + nt * 8 + tg * 2;
                float v0 = acc[mt][nt][half * 2];
                float v1 = acc[mt][nt][half * 2 + 1];
                if (EPI == 1) { v0 += bias[c]; v1 += bias[c + 1]; }
                if (EPI == 2) { v0 = tanhf(v0); v1 = tanhf(v1); }
                if (EPI == 3) {
                    v0 += bias[c]; v1 += bias[c + 1];
                    v0 = 0.5f * v0 * (1.0f + erff(v0 * 0.70710678118654752f));
                    v1 = 0.5f * v1 * (1.0f + erff(v1 * 0.70710678118654752f));
                }
                if (EPI == 4) {
                    const float2 rr = *(const float2*)(res + (size_t)m * ldc + c);
                    v0 += bias[c] + rr.x; v1 += bias[c + 1] + rr.y;
                }
                if (EPI == 5) {
                    const float2 rr = *(const float2*)(res + (size_t)m * ldc + c);
                    v0 = v0 * rinv + rr.x; v1 = v1 * rinv + rr.y;
                }
                if (EPI == 6) { v0 = ex2f(v0 * scale); v1 = ex2f(v1 * scale); rs += v0 + v1; }
                if (EPI == 7) { v0 = ex2f(fmaf(v0, a2v, a2v)); v1 = ex2f(fmaf(v1, a2v, a2v)); }
                if constexpr (OUTH) {
                    __half2 hv = __floats2half2_rn(v0, v1);
                    if (EPI == 6)
                        __stcs((__half2*)(C + (size_t)m * ldc + c), hv);
                    else
                        *(__half2*)(C + (size_t)m * ldc + c) = hv;
                } else {
                    float2 o; o.x = v0; o.y = v1;
                    *(float2*)(C + (size_t)m * ldc + c) = o;
                }
            }
            if (EPI == 6) {
                rs += __shfl_xor_sync(0xffffffffu, rs, 1);
                rs += __shfl_xor_sync(0xffffffffu, rs, 2);
                if (tg == 0) atomicAdd(&ssum[m], rs);
            }
        }
    }
}

// --------- blend: u = (mean_h softmax_h + 1e-6) * pcexp; rowsum --------------
__global__ void __launch_bounds__(256) blend_kernel(
    const __half* __restrict__ scoresE, const float* __restrict__ ssum,
    const __half* __restrict__ pcexp, __half* __restrict__ blend,
    float* __restrict__ rowsum)
{
    __shared__ float sm[8];
    __shared__ float sinvl[NH];
    int b = blockIdx.x / SEQ;
    int i = blockIdx.x - b * SEQ;
    if (threadIdx.x < NH)
        sinvl[threadIdx.x] = 1.0f / (ssum[(b * NH + threadIdx.x) * SEQ + i] * (float)NH);
    __syncthreads();

    int j = threadIdx.x * 8;
    const __half* ebase = scoresE + (((size_t)(b * NH)) * SEQ + i) * SEQ + j;
    float w[8];
#pragma unroll
    for (int q = 0; q < 8; q++) w[q] = 1e-6f;
#pragma unroll
    for (int h = 0; h < NH; h++) {
        uint4 ev = __ldcs((const uint4*)(ebase + (size_t)h * SEQ * SEQ));
        const __half2* eh = (const __half2*)&ev;
        float sl = sinvl[h];
#pragma unroll
        for (int q = 0; q < 4; q++) {
            float2 f = __half22float2(eh[q]);
            w[2*q]   = fmaf(f.x, sl, w[2*q]);
            w[2*q+1] = fmaf(f.y, sl, w[2*q+1]);
        }
    }
    uint4 pv = __ldcs((const uint4*)(pcexp + ((size_t)b * SEQ + i) * SEQ + j));
    const __half2* ph = (const __half2*)&pv;
    __half2 ov[4];
    float lsum = 0.0f;
#pragma unroll
    for (int q = 0; q < 4; q++) {
        float2 p = __half22float2(ph[q]);
        float u0 = w[2*q] * p.x, u1 = w[2*q+1] * p.y;
        ov[q] = __floats2half2_rn(u0, u1);
        lsum += u0 + u1;
    }
    *(uint4*)(blend + ((size_t)b * SEQ + i) * SEQ + j) = *(uint4*)ov;
    lsum = blockReduceSum256(lsum, sm);
    if (threadIdx.x == 0) rowsum[blockIdx.x] = lsum;
}

// ---------------------------------------------------------------------------
extern "C" void kernel_launch(void* const* d_in, const int* in_sizes, int n_in,
                              void* d_out, int out_size)
{
    const float* x        = (const float*)d_in[0];
    const float* ln1_w    = (const float*)d_in[1];
    const float* ln1_b    = (const float*)d_in[2];
    const float* in_w     = (const float*)d_in[3];
    const float* in_b     = (const float*)d_in[4];
    const float* phase_w  = (const float*)d_in[5];
    const float* alpha    = (const float*)d_in[6];
    const float* ff_w1    = (const float*)d_in[7];
    const float* ff_b1    = (const float*)d_in[8];
    const float* ff_w2    = (const float*)d_in[9];
    const float* ff_b2    = (const float*)d_in[10];
    const float* ln2_w    = (const float*)d_in[11];
    const float* ln2_b    = (const float*)d_in[12];
    float* out            = (float*)d_out;

    __half *xn, *xnT, *qk, *phw, *phase, *scores, *pcv, *blend, *x2, *hbuf,
           *inw, *w1, *w2;
    float *ssum, *rowsum, *xmid;
    cudaGetSymbolAddress((void**)&xn,     g_xn);
    cudaGetSymbolAddress((void**)&xnT,    g_xnT);
    cudaGetSymbolAddress((void**)&qk,     g_qk);
    cudaGetSymbolAddress((void**)&phw,    g_phw);
    cudaGetSymbolAddress((void**)&phase,  g_phase);
    cudaGetSymbolAddress((void**)&scores, g_scores);
    cudaGetSymbolAddress((void**)&ssum,   g_ssum);
    cudaGetSymbolAddress((void**)&pcv,    g_pc);
    cudaGetSymbolAddress((void**)&blend,  g_blend);
    cudaGetSymbolAddress((void**)&rowsum, g_rowsum);
    cudaGetSymbolAddress((void**)&xmid,   g_xmid);
    cudaGetSymbolAddress((void**)&x2,     g_x2);
    cudaGetSymbolAddress((void**)&hbuf,   g_hbuf);
    cudaGetSymbolAddress((void**)&inw,    g_inw);
    cudaGetSymbolAddress((void**)&w1,     g_w1);
    cudaGetSymbolAddress((void**)&w2,     g_w2);

    cudaFuncSetAttribute((const void*)tgemm<1,64>,  cudaFuncAttributeMaxDynamicSharedMemorySize, SMEM_64);
    cudaFuncSetAttribute((const void*)tgemm<2,64>,  cudaFuncAttributeMaxDynamicSharedMemorySize, SMEM_64);
    cudaFuncSetAttribute((const void*)tgemm<6,128>, cudaFuncAttributeMaxDynamicSharedMemorySize, SMEM_128);
    cudaFuncSetAttribute((const void*)tgemm<7,128>, cudaFuncAttributeMaxDynamicSharedMemorySize, SMEM_128);
    cudaFuncSetAttribute((const void*)tgemm<5,64>,  cudaFuncAttributeMaxDynamicSharedMemorySize, SMEM_64);
    cudaFuncSetAttribute((const void*)tgemm<3,128>, cudaFuncAttributeMaxDynamicSharedMemorySize, SMEM_128);
    cudaFuncSetAttribute((const void*)tgemm<4,64>,  cudaFuncAttributeMaxDynamicSharedMemorySize, SMEM_64);

    // 0) all weight rounding + padding + ssum zero in ONE kernel
    prep_kernel<<<(FFD*DIM + 255)/256, 256>>>(
        in_w, inw, ff_w1, w1, ff_w2, w2, phase_w, phw, ssum);

    // 1) xn = LN1(x) -> fp16 (warp-per-row); xnT
    ln_kernel<<<NROW/8, 256>>>(x, ln1_w, ln1_b, xn);
    transpose_kernel<<<dim3(SEQ/32, DIM/32, BB), 256>>>(xn, xnT);

    // 2) qk = xn @ W[0:1536]^T + b -> fp16   [4096, 1536], BN=64 (768 CTAs)
    tgemm<1,64><<<dim3(NROW/128, 1536/64, 1), 256, SMEM_64>>>(
        xn, inw, qk, NROW, 2*DIM, DIM, DIM, DIM, 2*DIM,
        1, 0,0, 0,0, 0,0, 1.0f, in_b, nullptr, 0, nullptr, 0, nullptr, nullptr);

    // 3) phase = tanh(xn @ phw^T) -> fp16    [4096, 128], BN=64 (64 CTAs)
    tgemm<2,64><<<dim3(NROW/128, PDPAD/64, 1), 256, SMEM_64>>>(
        xn, phw, phase, NROW, PDPAD, DIM, DIM, DIM, PDPAD,
        1, 0,0, 0,0, 0,0, 1.0f, nullptr, nullptr, 0, nullptr, 0, nullptr, nullptr);

    // 4) scores e = ex2(log2e/8 * q@k^T) -> fp16 (streaming) + rowsums
    tgemm<6,128><<<dim3(SEQ/128, SEQ/128, BB*NH), 256, SMEM_128>>>(
        qk, qk + DIM, scores, SEQ, SEQ, DHD, 2*DIM, 2*DIM, SEQ,
        NH, (long)SEQ*2*DIM, (long)DHD, (long)SEQ*2*DIM, (long)DHD,
            (long)NH*SEQ*SEQ, (long)SEQ*SEQ,
        0.125f * LOG2E, nullptr, nullptr, 0, nullptr, 0, nullptr, ssum);

    // 5) pcexp = ex2(a2l*(phase@phase^T) + a2l) -> fp16  2x[2048,2048], K=64
    tgemm<7,128><<<dim3(SEQ/128, SEQ/128, BB), 256, SMEM_128>>>(
        phase, phase, pcv, SEQ, SEQ, PDIM, PDPAD, PDPAD, SEQ,
        1, (long)SEQ*PDPAD, 0, (long)SEQ*PDPAD, 0, (long)SEQ*SEQ, 0,
        1.0f, nullptr, nullptr, 0, nullptr, 0, alpha, nullptr);

    // 6) blend weights (fp16) + row sums
    blend_kernel<<<BB*SEQ, 256>>>(scores, ssum, pcv, blend, rowsum);

    // 7) xmid = x + (blend/rowsum) @ xnT^T -> fp32, BN=64 (384 CTAs)
    tgemm<5,64><<<dim3(SEQ/128, DIM/64, BB), 256, SMEM_64>>>(
        blend, xnT, xmid, SEQ, DIM, SEQ, SEQ, SEQ, DIM,
        1, (long)SEQ*SEQ, 0, (long)DIM*SEQ, 0, (long)SEQ*DIM, 0,
        1.0f, nullptr, x, (long)SEQ*DIM, rowsum, (long)SEQ, nullptr, nullptr);

    // 8) x2 = LN2(xmid) -> fp16 (warp-per-row)
    ln_kernel<<<NROW/8, 256>>>(xmid, ln2_w, ln2_b, x2);

    // 9) h = gelu(x2 @ ff_w1^T + b1) -> fp16  [4096, 3072]
    tgemm<3,128><<<dim3(NROW/128, FFD/128, 1), 256, SMEM_128>>>(
        x2, w1, hbuf, NROW, FFD, DIM, DIM, DIM, FFD,
        1, 0,0, 0,0, 0,0, 1.0f, ff_b1, nullptr, 0, nullptr, 0, nullptr, nullptr);

    // 10) out = xmid + h @ ff_w2^T + b2 -> fp32, BN=64 (384 CTAs)
    tgemm<4,64><<<dim3(NROW/128, DIM/64, 1), 256, SMEM_64>>>(
        hbuf, w2, out, NROW, DIM, FFD, FFD, FFD, DIM,
        1, 0,0, 0,0, 0,0, 1.0f, ff_b2, xmid, 0, nullptr, 0, nullptr, nullptr);

    (void)in_sizes; (void)n_in; (void)out_size;
}